// round 13
// baseline (speedup 1.0000x reference)
#include <cuda_runtime.h>
#include <cuda_bf16.h>
#include <cstdint>
#include <cstring>
#include <math.h>

// Problem constants
#define BS 2
#define NPTS 1024
#define H 8
#define DH 64
#define KNB 16
#define EMB 512
#define INNER 512
#define AINNER 256
#define POSH 64

// ---------------- scratch (static device globals; no allocation) ----------------
__device__ float g_qh[BS * H * NPTS * DH];
__device__ float g_kh[BS * H * NPTS * DH];
__device__ float g_vh[BS * H * NPTS * DH];
__device__ int   g_nbr[BS * NPTS * KNB];
__device__ float g_rpe[BS * NPTS * KNB * INNER];
__device__ float g_attn[BS * H * NPTS * KNB * DH];
__device__ float g_norm[BS * H * KNB * DH];
__device__ __nv_bfloat16 g_aggh[BS * NPTS * INNER];   // agg bf16 hi plane
__device__ __nv_bfloat16 g_aggl[BS * NPTS * INNER];   // agg bf16 lo plane
// precomputed per-head attn weight planes (layouts match attn smem)
__device__ __nv_bfloat16 g_w1h[H * 256 * 72];
__device__ __nv_bfloat16 g_w1l[H * 256 * 72];
__device__ __nv_bfloat16 g_w2h[H * 64 * 264];
__device__ __nv_bfloat16 g_w2l[H * 64 * 264];

// ---------------- shared helpers ----------------
__device__ __forceinline__ uint32_t smem_u32(const void* p) {
    uint32_t a;
    asm("{ .reg .u64 tmp; cvta.to.shared.u64 tmp, %1; cvt.u32.u64 %0, tmp; }"
        : "=r"(a) : "l"(p));
    return a;
}

__device__ __forceinline__ void ldsm4p(uint32_t* r, uint32_t addr) {
    asm volatile("ldmatrix.sync.aligned.m8n8.x4.shared.b16 {%0,%1,%2,%3}, [%4];"
                 : "=r"(r[0]), "=r"(r[1]), "=r"(r[2]), "=r"(r[3])
                 : "r"(addr));
}

__device__ __forceinline__ void ldsm4t(uint32_t* r, uint32_t addr) {
    asm volatile("ldmatrix.sync.aligned.m8n8.x4.trans.shared.b16 {%0,%1,%2,%3}, [%4];"
                 : "=r"(r[0]), "=r"(r[1]), "=r"(r[2]), "=r"(r[3])
                 : "r"(addr));
}

__device__ __forceinline__ void mmabf(float* c, const uint32_t* a, uint32_t b0, uint32_t b1) {
    asm volatile("mma.sync.aligned.m16n8k16.row.col.f32.bf16.bf16.f32 "
                 "{%0,%1,%2,%3}, {%4,%5,%6,%7}, {%8,%9}, {%0,%1,%2,%3};"
                 : "+f"(c[0]), "+f"(c[1]), "+f"(c[2]), "+f"(c[3])
                 : "r"(a[0]), "r"(a[1]), "r"(a[2]), "r"(a[3]), "r"(b0), "r"(b1));
}

__device__ __forceinline__ void split_pair(float v0, float v1, uint32_t* hi, uint32_t* lo) {
    __nv_bfloat162 hv = __floats2bfloat162_rn(v0, v1);
    float f0 = __low2float(hv);
    float f1 = __high2float(hv);
    __nv_bfloat162 lv = __floats2bfloat162_rn(v0 - f0, v1 - f1);
    uint32_t uh, ul;
    memcpy(&uh, &hv, 4);
    memcpy(&ul, &lv, 4);
    *hi = uh;
    *lo = ul;
}

// ---------------- fused prologue: proj GEMMs + KNN + wprep ----------------
// grid.x partition: [0,768) proj (n=8, m=32, z=3); [768,1024) knn; [1024,1088) wprep
__global__ void __launch_bounds__(256)
pre_kernel(const float* __restrict__ query, const float* __restrict__ w_q,
           const float* __restrict__ key_in, const float* __restrict__ w_k,
           const float* __restrict__ value, const float* __restrict__ w_v,
           const float* __restrict__ canonical,
           const float* __restrict__ aw1, const float* __restrict__ aw2) {
    int bx = blockIdx.x;
    int t = threadIdx.x;

    if (bx < 768) {
        // ---- projection GEMM tile ----
        int z = bx >> 8;
        int rem = bx & 255;
        int n0 = (rem & 7) * 64;
        int m0 = (rem >> 3) * 64;
        const float* A = (z == 0) ? query : (z == 1) ? key_in : value;
        const float* B = (z == 0) ? w_q : (z == 1) ? w_k : w_v;
        float* C = (z == 0) ? g_qh : (z == 1) ? g_kh : g_vh;

        __shared__ __nv_bfloat16 Ah[64 * 40];
        __shared__ __nv_bfloat16 Al[64 * 40];
        __shared__ __nv_bfloat16 Bh[32 * 72];
        __shared__ __nv_bfloat16 Bl[32 * 72];

        int w = t >> 5;
        int lane = t & 31;
        int wm = w & 3;
        int wn = w >> 2;
        uint32_t ah_b = smem_u32(Ah);
        uint32_t al_b = smem_u32(Al);
        uint32_t bh_b = smem_u32(Bh);
        uint32_t bl_b = smem_u32(Bl);

        float acc[4][4];
#pragma unroll
        for (int nt = 0; nt < 4; nt++) {
#pragma unroll
            for (int q = 0; q < 4; q++) acc[nt][q] = 0.f;
        }

        int rr = lane & 7;
        int g = lane >> 3;
        int a_row = wm * 16 + rr + (g & 1) * 8;
        int a_colg = (g >> 1) * 8;
        int b_krow = lane & 15;
        int b_ng = (lane >> 4) * 8;

        for (int k0 = 0; k0 < 512; k0 += 32) {
#pragma unroll
            for (int p = 0; p < 2; p++) {
                int idx = t + p * 256;
                int m = idx >> 3;
                int c4 = (idx & 7) * 4;
                float4 v = *(const float4*)&A[(size_t)(m0 + m) * 512 + k0 + c4];
                uint32_t h01, l01, h23, l23;
                split_pair(v.x, v.y, &h01, &l01);
                split_pair(v.z, v.w, &h23, &l23);
                int eo = m * 40 + c4;
                *(uint32_t*)&Ah[eo] = h01;
                *(uint32_t*)&Ah[eo + 2] = h23;
                *(uint32_t*)&Al[eo] = l01;
                *(uint32_t*)&Al[eo + 2] = l23;
            }
#pragma unroll
            for (int p = 0; p < 2; p++) {
                int idx = t + p * 256;
                int k = idx >> 4;
                int n4 = (idx & 15) * 4;
                float4 v = *(const float4*)&B[(size_t)(k0 + k) * 512 + n0 + n4];
                uint32_t h01, l01, h23, l23;
                split_pair(v.x, v.y, &h01, &l01);
                split_pair(v.z, v.w, &h23, &l23);
                int eo = k * 72 + n4;
                *(uint32_t*)&Bh[eo] = h01;
                *(uint32_t*)&Bh[eo + 2] = h23;
                *(uint32_t*)&Bl[eo] = l01;
                *(uint32_t*)&Bl[eo + 2] = l23;
            }
            __syncthreads();

#pragma unroll
            for (int ks = 0; ks < 32; ks += 16) {
                uint32_t ahi[4];
                uint32_t alo[4];
                uint32_t aoff = (uint32_t)((a_row * 40 + ks + a_colg) * 2);
                ldsm4p(ahi, ah_b + aoff);
                ldsm4p(alo, al_b + aoff);
#pragma unroll
                for (int nh = 0; nh < 2; nh++) {
                    uint32_t bhv[4];
                    uint32_t blv[4];
                    uint32_t boff = (uint32_t)(((ks + b_krow) * 72 + wn * 32 + nh * 16 + b_ng) * 2);
                    ldsm4t(bhv, bh_b + boff);
                    ldsm4t(blv, bl_b + boff);
                    mmabf(acc[nh * 2], ahi, bhv[0], bhv[1]);
                    mmabf(acc[nh * 2], ahi, blv[0], blv[1]);
                    mmabf(acc[nh * 2], alo, bhv[0], bhv[1]);
                    mmabf(acc[nh * 2 + 1], ahi, bhv[2], bhv[3]);
                    mmabf(acc[nh * 2 + 1], ahi, blv[2], blv[3]);
                    mmabf(acc[nh * 2 + 1], alo, bhv[2], bhv[3]);
                }
            }
            __syncthreads();
        }

        int r = lane >> 2;
        int cq = lane & 3;
#pragma unroll
        for (int nt = 0; nt < 4; nt++) {
            int col = n0 + wn * 32 + nt * 8 + 2 * cq;
            int row0 = m0 + wm * 16 + r;
            int row1 = row0 + 8;
            int hh = (col >> 6) & 7;
            int dd = col & 63;
            int b0i = row0 >> 10, i0 = row0 & 1023;
            int b1i = row1 >> 10, i1 = row1 & 1023;
            *(float2*)&C[(((size_t)(b0i * H + hh) * NPTS) + i0) * DH + dd] =
                make_float2(acc[nt][0], acc[nt][1]);
            *(float2*)&C[(((size_t)(b1i * H + hh) * NPTS) + i1) * DH + dd] =
                make_float2(acc[nt][2], acc[nt][3]);
        }
    } else if (bx < 1024) {
        // ---- KNN block ----
        int kb = bx - 768;
        __shared__ float sx[NPTS], sy[NPTS], sz[NPTS];
        int b = kb >> 7;
        int wid = t >> 5, lane = t & 31;
        for (int p = t; p < NPTS; p += 256) {
            sx[p] = canonical[(b * NPTS + p) * 3 + 0];
            sy[p] = canonical[(b * NPTS + p) * 3 + 1];
            sz[p] = canonical[(b * NPTS + p) * 3 + 2];
        }
        __syncthreads();
        int i = (kb & 127) * 8 + wid;
        float qx = sx[i], qy = sy[i], qz = sz[i];
        float prev_d = -1.f;
        int prev_j = -1;
        for (int s = 0; s < KNB; s++) {
            float bd = INFINITY;
            int bj = 1 << 30;
            for (int p = lane; p < NPTS; p += 32) {
                float dx = sx[p] - qx, dy = sy[p] - qy, dz = sz[p] - qz;
                float d2 = dx * dx + dy * dy + dz * dz;
                bool gt_prev = (d2 > prev_d) || (d2 == prev_d && p > prev_j);
                bool lt_best = (d2 < bd) || (d2 == bd && p < bj);
                if (gt_prev && lt_best) { bd = d2; bj = p; }
            }
#pragma unroll
            for (int off = 16; off; off >>= 1) {
                float od = __shfl_down_sync(0xFFFFFFFFu, bd, off);
                int   oj = __shfl_down_sync(0xFFFFFFFFu, bj, off);
                if (od < bd || (od == bd && oj < bj)) { bd = od; bj = oj; }
            }
            bd = __shfl_sync(0xFFFFFFFFu, bd, 0);
            bj = __shfl_sync(0xFFFFFFFFu, bj, 0);
            if (lane == 0) g_nbr[(b * NPTS + i) * KNB + s] = bj;
            prev_d = bd;
            prev_j = bj;
        }
    } else {
        // ---- wprep slice: 64 blocks = (h, seg) ----
        int wb = bx - 1024;
        int h = wb >> 3;
        int seg = wb & 7;
        for (int k = 0; k < 8; k++) {
            int idx = seg * 2048 + k * 256 + t;   // [0, 16384)
            int e = idx >> 6;
            int d = idx & 63;
            float v = aw1[(h * AINNER + e) * DH + d];
            __nv_bfloat16 hi = __float2bfloat16_rn(v);
            g_w1h[h * 256 * 72 + e * 72 + d] = hi;
            g_w1l[h * 256 * 72 + e * 72 + d] = __float2bfloat16_rn(v - __bfloat162float(hi));
        }
        for (int k = 0; k < 8; k++) {
            int idx = seg * 2048 + k * 256 + t;
            int d = idx >> 8;
            int e = idx & 255;
            float v = aw2[(h * DH + d) * AINNER + e];
            __nv_bfloat16 hi = __float2bfloat16_rn(v);
            g_w2h[h * 64 * 264 + d * 264 + e] = hi;
            g_w2l[h * 64 * 264 + d * 264 + e] = __float2bfloat16_rn(v - __bfloat162float(hi));
        }
    }
}

// ---------------- output GEMM: out[2048,512] = agg(planes) @ w_out + b_out ----------------
__global__ void __launch_bounds__(256)
out_gemm(const float* __restrict__ B,
         const float* __restrict__ bias, float* __restrict__ C) {
    __shared__ __nv_bfloat16 Ah[64 * 40];
    __shared__ __nv_bfloat16 Al[64 * 40];
    __shared__ __nv_bfloat16 Bh[32 * 72];
    __shared__ __nv_bfloat16 Bl[32 * 72];

    int t = threadIdx.x;
    int w = t >> 5;
    int lane = t & 31;
    int wm = w & 3;
    int wn = w >> 2;
    int m0 = blockIdx.y * 64;
    int n0 = blockIdx.x * 64;

    uint32_t ah_b = smem_u32(Ah);
    uint32_t al_b = smem_u32(Al);
    uint32_t bh_b = smem_u32(Bh);
    uint32_t bl_b = smem_u32(Bl);

    float acc[4][4];
#pragma unroll
    for (int nt = 0; nt < 4; nt++) {
#pragma unroll
        for (int q = 0; q < 4; q++) acc[nt][q] = 0.f;
    }

    int rr = lane & 7;
    int g = lane >> 3;
    int a_row = wm * 16 + rr + (g & 1) * 8;
    int a_colg = (g >> 1) * 8;
    int b_krow = lane & 15;
    int b_ng = (lane >> 4) * 8;

    for (int k0 = 0; k0 < 512; k0 += 32) {
        // A planes: straight copies (split precomputed by agg_kernel)
#pragma unroll
        for (int p = 0; p < 2; p++) {
            int idx = t + p * 256;
            int m = idx >> 3;
            int c4 = (idx & 7) * 4;
            size_t go = (size_t)(m0 + m) * 512 + k0 + c4;
            uint2 vh_ = *(const uint2*)&g_aggh[go];
            uint2 vl_ = *(const uint2*)&g_aggl[go];
            int eo = m * 40 + c4;
            *(uint32_t*)&Ah[eo] = vh_.x;
            *(uint32_t*)&Ah[eo + 2] = vh_.y;
            *(uint32_t*)&Al[eo] = vl_.x;
            *(uint32_t*)&Al[eo + 2] = vl_.y;
        }
#pragma unroll
        for (int p = 0; p < 2; p++) {
            int idx = t + p * 256;
            int k = idx >> 4;
            int n4 = (idx & 15) * 4;
            float4 v = *(const float4*)&B[(size_t)(k0 + k) * 512 + n0 + n4];
            uint32_t h01, l01, h23, l23;
            split_pair(v.x, v.y, &h01, &l01);
            split_pair(v.z, v.w, &h23, &l23);
            int eo = k * 72 + n4;
            *(uint32_t*)&Bh[eo] = h01;
            *(uint32_t*)&Bh[eo + 2] = h23;
            *(uint32_t*)&Bl[eo] = l01;
            *(uint32_t*)&Bl[eo + 2] = l23;
        }
        __syncthreads();

#pragma unroll
        for (int ks = 0; ks < 32; ks += 16) {
            uint32_t ahi[4];
            uint32_t alo[4];
            uint32_t aoff = (uint32_t)((a_row * 40 + ks + a_colg) * 2);
            ldsm4p(ahi, ah_b + aoff);
            ldsm4p(alo, al_b + aoff);
#pragma unroll
            for (int nh = 0; nh < 2; nh++) {
                uint32_t bhv[4];
                uint32_t blv[4];
                uint32_t boff = (uint32_t)(((ks + b_krow) * 72 + wn * 32 + nh * 16 + b_ng) * 2);
                ldsm4t(bhv, bh_b + boff);
                ldsm4t(blv, bl_b + boff);
                mmabf(acc[nh * 2], ahi, bhv[0], bhv[1]);
                mmabf(acc[nh * 2], ahi, blv[0], blv[1]);
                mmabf(acc[nh * 2], alo, bhv[0], bhv[1]);
                mmabf(acc[nh * 2 + 1], ahi, bhv[2], bhv[3]);
                mmabf(acc[nh * 2 + 1], ahi, blv[2], blv[3]);
                mmabf(acc[nh * 2 + 1], alo, bhv[2], bhv[3]);
            }
        }
        __syncthreads();
    }

    int r = lane >> 2;
    int cq = lane & 3;
#pragma unroll
    for (int nt = 0; nt < 4; nt++) {
        int col = n0 + wn * 32 + nt * 8 + 2 * cq;
        int row0 = m0 + wm * 16 + r;
        int row1 = row0 + 8;
        float bz0 = bias[col];
        float bz1 = bias[col + 1];
        *(float2*)&C[(size_t)row0 * 512 + col] = make_float2(acc[nt][0] + bz0, acc[nt][1] + bz1);
        *(float2*)&C[(size_t)row1 * 512 + col] = make_float2(acc[nt][2] + bz0, acc[nt][3] + bz1);
    }
}

// ---------------- rpe GEMM with fused h1: rpe = relu(rel@pw1+pb1) @ pw2 + pb2 ----------------
// B (pw2, full K=64) resident in smem; 8 M-tiles per block; A computed in-place. grid (8, 64).
__global__ void __launch_bounds__(256)
rpe_gemm(const float* __restrict__ canonical,
         const float* __restrict__ pw1, const float* __restrict__ pb1,
         const float* __restrict__ pw2, const float* __restrict__ pb2) {
    __shared__ __nv_bfloat16 Bh[64 * 72];
    __shared__ __nv_bfloat16 Bl[64 * 72];
    __shared__ __nv_bfloat16 Ah[64 * 72];
    __shared__ __nv_bfloat16 Al[64 * 72];
    __shared__ float spw1[192];
    __shared__ float spb1[64];
    __shared__ float relS[64][3];

    int t = threadIdx.x;
    int w = t >> 5;
    int lane = t & 31;
    int wm = w & 3;
    int wn = w >> 2;
    int n0 = blockIdx.x * 64;

    uint32_t ah_b = smem_u32(Ah);
    uint32_t al_b = smem_u32(Al);
    uint32_t bh_b = smem_u32(Bh);
    uint32_t bl_b = smem_u32(Bl);

    if (t < 192) spw1[t] = pw1[t];
    else spb1[t - 192] = pb1[t - 192];

#pragma unroll
    for (int p = 0; p < 4; p++) {
        int idx = t + p * 256;
        int k = idx >> 4;
        int n4 = (idx & 15) * 4;
        float4 v = *(const float4*)&pw2[(size_t)k * 512 + n0 + n4];
        uint32_t h01, l01, h23, l23;
        split_pair(v.x, v.y, &h01, &l01);
        split_pair(v.z, v.w, &h23, &l23);
        int eo = k * 72 + n4;
        *(uint32_t*)&Bh[eo] = h01;
        *(uint32_t*)&Bh[eo + 2] = h23;
        *(uint32_t*)&Bl[eo] = l01;
        *(uint32_t*)&Bl[eo + 2] = l23;
    }

    int rr = lane & 7;
    int g = lane >> 3;
    int a_row = wm * 16 + rr + (g & 1) * 8;
    int a_colg = (g >> 1) * 8;
    int b_krow = lane & 15;
    int b_ng = (lane >> 4) * 8;
    int r = lane >> 2;
    int cq = lane & 3;

    for (int mt = 0; mt < 8; mt++) {
        int m0 = (blockIdx.y * 8 + mt) * 64;

        // rel for the 64 rows of this tile: row ri -> (bi = ri>>4, j = ri&15)
        if (t < 64) {
            int ri = m0 + t;
            int bi = ri >> 4;
            int j = ri & 15;
            int b = bi >> 10;
            int nv = g_nbr[bi * KNB + j];
#pragma unroll
            for (int c = 0; c < 3; c++) {
                relS[t][c] = canonical[(b * NPTS + nv) * 3 + c] - canonical[bi * 3 + c];
            }
        }
        __syncthreads();

        // A tile = relu(rel @ pw1 + pb1), split into planes
#pragma unroll
        for (int p = 0; p < 4; p++) {
            int idx = t + p * 256;
            int m = idx >> 4;
            int c4 = (idx & 15) * 4;
            float r0 = relS[m][0];
            float r1 = relS[m][1];
            float r2 = relS[m][2];
            float v0 = fmaxf(r0 * spw1[c4 + 0] + r1 * spw1[64 + c4 + 0] + r2 * spw1[128 + c4 + 0] + spb1[c4 + 0], 0.f);
            float v1 = fmaxf(r0 * spw1[c4 + 1] + r1 * spw1[64 + c4 + 1] + r2 * spw1[128 + c4 + 1] + spb1[c4 + 1], 0.f);
            float v2 = fmaxf(r0 * spw1[c4 + 2] + r1 * spw1[64 + c4 + 2] + r2 * spw1[128 + c4 + 2] + spb1[c4 + 2], 0.f);
            float v3 = fmaxf(r0 * spw1[c4 + 3] + r1 * spw1[64 + c4 + 3] + r2 * spw1[128 + c4 + 3] + spb1[c4 + 3], 0.f);
            uint32_t h01, l01, h23, l23;
            split_pair(v0, v1, &h01, &l01);
            split_pair(v2, v3, &h23, &l23);
            int eo = m * 72 + c4;
            *(uint32_t*)&Ah[eo] = h01;
            *(uint32_t*)&Ah[eo + 2] = h23;
            *(uint32_t*)&Al[eo] = l01;
            *(uint32_t*)&Al[eo + 2] = l23;
        }
        __syncthreads();

        float acc[4][4];
#pragma unroll
        for (int nt = 0; nt < 4; nt++) {
#pragma unroll
            for (int q = 0; q < 4; q++) acc[nt][q] = 0.f;
        }

#pragma unroll
        for (int ks = 0; ks < 64; ks += 16) {
            uint32_t ahi[4];
            uint32_t alo[4];
            uint32_t aoff = (uint32_t)((a_row * 72 + ks + a_colg) * 2);
            ldsm4p(ahi, ah_b + aoff);
            ldsm4p(alo, al_b + aoff);
#pragma unroll
            for (int nh = 0; nh < 2; nh++) {
                uint32_t bhv[4];
                uint32_t blv[4];
                uint32_t boff = (uint32_t)(((ks + b_krow) * 72 + wn * 32 + nh * 16 + b_ng) * 2);
                ldsm4t(bhv, bh_b + boff);
                ldsm4t(blv, bl_b + boff);
                mmabf(acc[nh * 2], ahi, bhv[0], bhv[1]);
                mmabf(acc[nh * 2], ahi, blv[0], blv[1]);
                mmabf(acc[nh * 2], alo, bhv[0], bhv[1]);
                mmabf(acc[nh * 2 + 1], ahi, bhv[2], bhv[3]);
                mmabf(acc[nh * 2 + 1], ahi, blv[2], blv[3]);
                mmabf(acc[nh * 2 + 1], alo, bhv[2], bhv[3]);
            }
        }

#pragma unroll
        for (int nt = 0; nt < 4; nt++) {
            int col = n0 + wn * 32 + nt * 8 + 2 * cq;
            int row0 = m0 + wm * 16 + r;
            int row1 = row0 + 8;
            float bz0 = pb2[col];
            float bz1 = pb2[col + 1];
            *(float2*)&g_rpe[(size_t)row0 * 512 + col] = make_float2(acc[nt][0] + bz0, acc[nt][1] + bz1);
            *(float2*)&g_rpe[(size_t)row1 * 512 + col] = make_float2(acc[nt][2] + bz0, acc[nt][3] + bz1);
        }
        __syncthreads();
    }
}

// faithful replication of the reference's flattened-view gather
__device__ __forceinline__ int gather_row(int b, int h, int i, int j) {
    int m = 2 * i + (j >> 3);
    int ip = h * 128 + (m >> 4);
    int jp = m & 15;
    int nv = g_nbr[(b * NPTS + ip) * KNB + jp];
    int cc = nv * 8 + (j & 7);
    int h2 = cc >> 10;
    int i2 = cc & 1023;
    return ((b * H + h2) * NPTS + i2) * DH;
}

// smem layout (bytes) for attn
#define AT_W1H 0
#define AT_W1L 36864
#define AT_W2H 73728
#define AT_W2L 107520
#define AT_X   141312
#define AT_AB1 178176
#define AT_AB2 179200
#define AT_SMEM 179456

// warp-per-i tensor-core attn MLP (bf16x3) + softmax. 32 i per block, h uniform.
__global__ void __launch_bounds__(256, 1)
attn_tc_kernel(const float* __restrict__ ab1, const float* __restrict__ ab2) {
    extern __shared__ char smem[];
    uint32_t sb = smem_u32(smem);
    int t = threadIdx.x;
    int w = t >> 5;
    int lane = t & 31;
    int h = ((blockIdx.x * 32) >> 10) & 7;

    {
        const uint4* s1h = (const uint4*)&g_w1h[h * 256 * 72];
        const uint4* s1l = (const uint4*)&g_w1l[h * 256 * 72];
        uint4* d1h = (uint4*)(smem + AT_W1H);
        uint4* d1l = (uint4*)(smem + AT_W1L);
        for (int idx = t; idx < 256 * 72 / 8; idx += 256) {
            d1h[idx] = s1h[idx];
            d1l[idx] = s1l[idx];
        }
        const uint4* s2h = (const uint4*)&g_w2h[h * 64 * 264];
        const uint4* s2l = (const uint4*)&g_w2l[h * 64 * 264];
        uint4* d2h = (uint4*)(smem + AT_W2H);
        uint4* d2l = (uint4*)(smem + AT_W2L);
        for (int idx = t; idx < 64 * 264 / 8; idx += 256) {
            d2h[idx] = s2h[idx];
            d2l[idx] = s2l[idx];
        }
    }
    float* sab1 = (float*)(smem + AT_AB1);
    float* sab2 = (float*)(smem + AT_AB2);
    sab1[t] = ab1[h * AINNER + t];
    if (t < 64) sab2[t] = ab2[h * DH + t];
    __syncthreads();

    int r  = lane >> 2;
    int cq = lane & 3;
    int rr = lane & 7;
    int g  = lane >> 3;
    uint32_t xh_base = sb + AT_X + w * 4608;
    uint32_t xl_base = xh_base + 2304;
    char* xh_ptr = smem + AT_X + w * 4608;
    char* xl_ptr = xh_ptr + 2304;
    uint32_t w1h_base = sb + AT_W1H;
    uint32_t w1l_base = sb + AT_W1L;
    uint32_t w2h_base = sb + AT_W2H;
    uint32_t w2l_base = sb + AT_W2L;

    for (int l = 0; l < 4; l++) {
        int bhi = blockIdx.x * 32 + w * 4 + l;
        int i = bhi & 1023;
        int b = bhi >> 13;

        int sr = 0;
        if (lane < 16) sr = gather_row(b, h, i, lane);

#pragma unroll
        for (int it = 0; it < 8; it++) {
            int idx = lane + it * 32;
            int j  = idx >> 4;
            int d4 = idx & 15;
            int ro = __shfl_sync(0xFFFFFFFFu, sr, j) + d4 * 4;
            float4 qv = *(const float4*)&g_qh[ro];
            float4 kv = *(const float4*)&g_kh[ro];
            float4 rv = *(const float4*)&g_rpe[((size_t)(b * NPTS + i) * KNB + j) * INNER + h * DH + d4 * 4];
            uint32_t h01, l01, h23, l23;
            split_pair(qv.x - kv.x + rv.x, qv.y - kv.y + rv.y, &h01, &l01);
            split_pair(qv.z - kv.z + rv.z, qv.w - kv.w + rv.w, &h23, &l23);
            int off = j * 144 + d4 * 8;
            *(uint32_t*)(xh_ptr + off)     = h01;
            *(uint32_t*)(xh_ptr + off + 4) = h23;
            *(uint32_t*)(xl_ptr + off)     = l01;
            *(uint32_t*)(xl_ptr + off + 4) = l23;
        }
        __syncwarp();

        float acc2[8][4];
#pragma unroll
        for (int nt2 = 0; nt2 < 8; nt2++) {
            int d0 = nt2 * 8 + 2 * cq;
            acc2[nt2][0] = sab2[d0];
            acc2[nt2][1] = sab2[d0 + 1];
            acc2[nt2][2] = acc2[nt2][0];
            acc2[nt2][3] = acc2[nt2][1];
        }

#pragma unroll
        for (int half = 0; half < 2; half++) {
            float acc1[16][4];
#pragma unroll
            for (int nt = 0; nt < 16; nt++) {
                int e0 = (half * 16 + nt) * 8 + 2 * cq;
                acc1[nt][0] = sab1[e0];
                acc1[nt][1] = sab1[e0 + 1];
                acc1[nt][2] = acc1[nt][0];
                acc1[nt][3] = acc1[nt][1];
            }
#pragma unroll
            for (int kt = 0; kt < 4; kt++) {
                uint32_t ahi[4];
                uint32_t alo[4];
                uint32_t aoff = (uint32_t)((rr + (g & 1) * 8) * 144 + (kt * 16 + (g >> 1) * 8) * 2);
                ldsm4p(ahi, xh_base + aoff);
                ldsm4p(alo, xl_base + aoff);
#pragma unroll
                for (int ntp = 0; ntp < 8; ntp++) {
                    int erow = (half * 16 + 2 * ntp + (g >> 1)) * 8 + rr;
                    int dcol = kt * 16 + (g & 1) * 8;
                    uint32_t boff = (uint32_t)(erow * 144 + dcol * 2);
                    uint32_t bhv[4];
                    uint32_t blv[4];
                    ldsm4p(bhv, w1h_base + boff);
                    ldsm4p(blv, w1l_base + boff);
                    mmabf(acc1[2 * ntp], ahi, bhv[0], bhv[1]);
                    mmabf(acc1[2 * ntp], ahi, blv[0], blv[1]);
                    mmabf(acc1[2 * ntp], alo, bhv[0], bhv[1]);
                    mmabf(acc1[2 * ntp + 1], ahi, bhv[2], bhv[3]);
                    mmabf(acc1[2 * ntp + 1], ahi, blv[2], blv[3]);
                    mmabf(acc1[2 * ntp + 1], alo, bhv[2], bhv[3]);
                }
            }
#pragma unroll
            for (int ap = 0; ap < 8; ap++) {
                float v0 = fmaxf(acc1[2 * ap][0], 0.f);
                float v1 = fmaxf(acc1[2 * ap][1], 0.f);
                float v2 = fmaxf(acc1[2 * ap][2], 0.f);
                float v3 = fmaxf(acc1[2 * ap][3], 0.f);
                float v4 = fmaxf(acc1[2 * ap + 1][0], 0.f);
                float v5 = fmaxf(acc1[2 * ap + 1][1], 0.f);
                float v6 = fmaxf(acc1[2 * ap + 1][2], 0.f);
                float v7 = fmaxf(acc1[2 * ap + 1][3], 0.f);
                uint32_t a2h[4];
                uint32_t a2l[4];
                split_pair(v0, v1, &a2h[0], &a2l[0]);
                split_pair(v2, v3, &a2h[1], &a2l[1]);
                split_pair(v4, v5, &a2h[2], &a2l[2]);
                split_pair(v6, v7, &a2h[3], &a2l[3]);
                int kcol = (half * 8 + ap) * 16;
#pragma unroll
                for (int np = 0; np < 4; np++) {
                    int drow = (2 * np + (g >> 1)) * 8 + rr;
                    int ecol = kcol + (g & 1) * 8;
                    uint32_t b2off = (uint32_t)(drow * 528 + ecol * 2);
                    uint32_t b2h[4];
                    uint32_t b2l[4];
                    ldsm4p(b2h, w2h_base + b2off);
                    ldsm4p(b2l, w2l_base + b2off);
                    mmabf(acc2[2 * np], a2h, b2h[0], b2h[1]);
                    mmabf(acc2[2 * np], a2h, b2l[0], b2l[1]);
                    mmabf(acc2[2 * np], a2l, b2h[0], b2h[1]);
                    mmabf(acc2[2 * np + 1], a2h, b2h[2], b2h[3]);
                    mmabf(acc2[2 * np + 1], a2h, b2l[2], b2l[3]);
                    mmabf(acc2[2 * np + 1], a2l, b2h[2], b2h[3]);
                }
            }
        }

        size_t base = (size_t)bhi * KNB * DH;
#pragma unroll
        for (int nt2 = 0; nt2 < 8; nt2++) {
            float c0 = acc2[nt2][0];
            float c1 = acc2[nt2][1];
            float c2 = acc2[nt2][2];
            float c3 = acc2[nt2][3];
            float ma = fmaxf(c0, c2);
            float mb = fmaxf(c1, c3);
#pragma unroll
            for (int mk = 4; mk <= 16; mk <<= 1) {
                ma = fmaxf(ma, __shfl_xor_sync(0xFFFFFFFFu, ma, mk));
                mb = fmaxf(mb, __shfl_xor_sync(0xFFFFFFFFu, mb, mk));
            }
            float e0 = expf(c0 - ma);
            float e2 = expf(c2 - ma);
            float e1 = expf(c1 - mb);
            float e3 = expf(c3 - mb);
            float sa = e0 + e2;
            float sc = e1 + e3;
#pragma unroll
            for (int mk = 4; mk <= 16; mk <<= 1) {
                sa += __shfl_xor_sync(0xFFFFFFFFu, sa, mk);
                sc += __shfl_xor_sync(0xFFFFFFFFu, sc, mk);
            }
            float ia = 1.f / sa;
            float ic = 1.f / sc;
            int d0 = nt2 * 8 + 2 * cq;
            *(float2*)&g_attn[base + (size_t)r * DH + d0] = make_float2(e0 * ia, e1 * ic);
            *(float2*)&g_attn[base + (size_t)(r + 8) * DH + d0] = make_float2(e2 * ia, e3 * ic);
        }
        __syncwarp();
    }
}

// ---------------- norm over i (1024 threads: 16 partial sums of 64 i's) ----------------
__global__ void __launch_bounds__(1024)
norm_kernel() {
    int bhj = blockIdx.x;
    int j = bhj & 15;
    int bh = bhj >> 4;
    int t = threadIdx.x;
    int d = t & 63;
    int iq = t >> 6;       // 0..15
    size_t base = (size_t)bh * NPTS * KNB * DH + j * DH + d;
    float s = 0.f;
#pragma unroll 4
    for (int i = iq * 64; i < iq * 64 + 64; i++) {
        float v = g_attn[base + (size_t)i * KNB * DH];
        s += v * v;
    }
    __shared__ float rshared[16][64];
    rshared[iq][d] = s;
    __syncthreads();
    if (t < 64) {
        float acc = 0.f;
#pragma unroll
        for (int k = 0; k < 16; k++) acc += rshared[k][t];
        g_norm[bhj * DH + t] = sqrtf(acc);
    }
}

// ---------------- aggregate: writes bf16 hi/lo planes for out_gemm ----------------
__global__ void agg_kernel() {
    int t = threadIdx.x;
    int ii = t >> 6;
    int d = t & 63;
    int bhi = blockIdx.x * 4 + ii;
    int i = bhi & 1023;
    int h = (bhi >> 10) & 7;
    int b = bhi >> 13;

    __shared__ int srow[4][KNB];
    if (t < 64) {
        int i2 = t >> 4;
        int j = t & 15;
        srow[i2][j] = gather_row(b, h, (blockIdx.x * 4 + i2) & 1023, j);
    }
    __syncthreads();

    int bh = b * H + h;
    size_t abase = (size_t)bhi * KNB * DH + d;
    float acc = 0.f;
#pragma unroll
    for (int j = 0; j < KNB; j++) {
        float a = g_attn[abase + j * DH];
        float nm = g_norm[(bh * KNB + j) * DH + d];
        a /= fmaxf(nm, 1e-12f);
        float vg = g_vh[srow[ii][j] + d] +
                   g_rpe[(size_t)((b * NPTS + i) * KNB + j) * INNER + h * DH + d];
        acc = fmaf(a, vg, acc);
    }
    size_t go = (size_t)(b * NPTS + i) * INNER + h * DH + d;
    __nv_bfloat16 hi = __float2bfloat16_rn(acc);
    g_aggh[go] = hi;
    g_aggl[go] = __float2bfloat16_rn(acc - __bfloat162float(hi));
}

// ---------------- launch ----------------
extern "C" void kernel_launch(void* const* d_in, const int* in_sizes, int n_in,
                              void* d_out, int out_size) {
    const float* query     = (const float*)d_in[0];
    const float* key_in    = (const float*)d_in[1];
    const float* value     = (const float*)d_in[2];
    const float* canonical = (const float*)d_in[3];
    const float* w_q       = (const float*)d_in[4];
    const float* w_k       = (const float*)d_in[5];
    const float* w_v       = (const float*)d_in[6];
    const float* w_out     = (const float*)d_in[7];
    const float* b_out     = (const float*)d_in[8];
    const float* pos_w1    = (const float*)d_in[9];
    const float* pos_b1    = (const float*)d_in[10];
    const float* pos_w2    = (const float*)d_in[11];
    const float* pos_b2    = (const float*)d_in[12];
    const float* aw1       = (const float*)d_in[13];
    const float* ab1       = (const float*)d_in[14];
    const float* aw2       = (const float*)d_in[15];
    const float* ab2       = (const float*)d_in[16];
    float* out = (float*)d_out;

    cudaFuncSetAttribute(attn_tc_kernel,
                         cudaFuncAttributeMaxDynamicSharedMemorySize, AT_SMEM);

    // fused prologue: proj + knn + wprep (independent work, one wave)
    pre_kernel<<<1088, 256>>>(query, w_q, key_in, w_k, value, w_v,
                              canonical, aw1, aw2);

    // rpe with fused h1 layer
    dim3 rgrid(8, 64);
    rpe_gemm<<<rgrid, 256>>>(canonical, pos_w1, pos_b1, pos_w2, pos_b2);

    attn_tc_kernel<<<BS * H * NPTS / 32, 256, AT_SMEM>>>(ab1, ab2);
    norm_kernel<<<BS * H * KNB, 1024>>>();
    agg_kernel<<<BS * H * NPTS / 4, 256>>>();

    dim3 ogrid(8, 32, 1);
    out_gemm<<<ogrid, 256>>>(w_out, b_out, out);
}

// round 14
// speedup vs baseline: 1.0133x; 1.0133x over previous
#include <cuda_runtime.h>
#include <cuda_bf16.h>
#include <cstdint>
#include <cstring>
#include <math.h>

// Problem constants
#define BS 2
#define NPTS 1024
#define H 8
#define DH 64
#define KNB 16
#define EMB 512
#define INNER 512
#define AINNER 256
#define POSH 64

// ---------------- scratch (static device globals; no allocation) ----------------
__device__ float g_qh[BS * H * NPTS * DH];
__device__ float g_kh[BS * H * NPTS * DH];
__device__ float g_vh[BS * H * NPTS * DH];
__device__ int   g_nbr[BS * NPTS * KNB];
__device__ float g_h1[BS * NPTS * KNB * POSH];
__device__ float g_rpe[BS * NPTS * KNB * INNER];
__device__ float g_attn[BS * H * NPTS * KNB * DH];
__device__ float g_norm[BS * H * KNB * DH];
__device__ float g_agg[BS * NPTS * INNER];
// precomputed per-head attn weight planes (layouts match attn smem)
__device__ __nv_bfloat16 g_w1h[H * 256 * 72];
__device__ __nv_bfloat16 g_w1l[H * 256 * 72];
__device__ __nv_bfloat16 g_w2h[H * 64 * 264];
__device__ __nv_bfloat16 g_w2l[H * 64 * 264];

// ---------------- shared helpers ----------------
__device__ __forceinline__ uint32_t smem_u32(const void* p) {
    uint32_t a;
    asm("{ .reg .u64 tmp; cvta.to.shared.u64 tmp, %1; cvt.u32.u64 %0, tmp; }"
        : "=r"(a) : "l"(p));
    return a;
}

__device__ __forceinline__ void ldsm4p(uint32_t* r, uint32_t addr) {
    asm volatile("ldmatrix.sync.aligned.m8n8.x4.shared.b16 {%0,%1,%2,%3}, [%4];"
                 : "=r"(r[0]), "=r"(r[1]), "=r"(r[2]), "=r"(r[3])
                 : "r"(addr));
}

__device__ __forceinline__ void ldsm4t(uint32_t* r, uint32_t addr) {
    asm volatile("ldmatrix.sync.aligned.m8n8.x4.trans.shared.b16 {%0,%1,%2,%3}, [%4];"
                 : "=r"(r[0]), "=r"(r[1]), "=r"(r[2]), "=r"(r[3])
                 : "r"(addr));
}

__device__ __forceinline__ void mmabf(float* c, const uint32_t* a, uint32_t b0, uint32_t b1) {
    asm volatile("mma.sync.aligned.m16n8k16.row.col.f32.bf16.bf16.f32 "
                 "{%0,%1,%2,%3}, {%4,%5,%6,%7}, {%8,%9}, {%0,%1,%2,%3};"
                 : "+f"(c[0]), "+f"(c[1]), "+f"(c[2]), "+f"(c[3])
                 : "r"(a[0]), "r"(a[1]), "r"(a[2]), "r"(a[3]), "r"(b0), "r"(b1));
}

__device__ __forceinline__ void split_pair(float v0, float v1, uint32_t* hi, uint32_t* lo) {
    __nv_bfloat162 hv = __floats2bfloat162_rn(v0, v1);
    float f0 = __low2float(hv);
    float f1 = __high2float(hv);
    __nv_bfloat162 lv = __floats2bfloat162_rn(v0 - f0, v1 - f1);
    uint32_t uh, ul;
    memcpy(&uh, &hv, 4);
    memcpy(&ul, &lv, 4);
    *hi = uh;
    *lo = ul;
}

// ---------------- fused prologue: proj GEMMs + KNN + wprep ----------------
// grid.x partition: [0,768) proj (n=8, m=32, z=3); [768,1024) knn; [1024,1088) wprep
__global__ void __launch_bounds__(256)
pre_kernel(const float* __restrict__ query, const float* __restrict__ w_q,
           const float* __restrict__ key_in, const float* __restrict__ w_k,
           const float* __restrict__ value, const float* __restrict__ w_v,
           const float* __restrict__ canonical,
           const float* __restrict__ aw1, const float* __restrict__ aw2) {
    int bx = blockIdx.x;
    int t = threadIdx.x;

    if (bx < 768) {
        // ---- projection GEMM tile ----
        int z = bx >> 8;
        int rem = bx & 255;
        int n0 = (rem & 7) * 64;
        int m0 = (rem >> 3) * 64;
        const float* A = (z == 0) ? query : (z == 1) ? key_in : value;
        const float* B = (z == 0) ? w_q : (z == 1) ? w_k : w_v;
        float* C = (z == 0) ? g_qh : (z == 1) ? g_kh : g_vh;

        __shared__ __nv_bfloat16 Ah[64 * 40];
        __shared__ __nv_bfloat16 Al[64 * 40];
        __shared__ __nv_bfloat16 Bh[32 * 72];
        __shared__ __nv_bfloat16 Bl[32 * 72];

        int w = t >> 5;
        int lane = t & 31;
        int wm = w & 3;
        int wn = w >> 2;
        uint32_t ah_b = smem_u32(Ah);
        uint32_t al_b = smem_u32(Al);
        uint32_t bh_b = smem_u32(Bh);
        uint32_t bl_b = smem_u32(Bl);

        float acc[4][4];
#pragma unroll
        for (int nt = 0; nt < 4; nt++) {
#pragma unroll
            for (int q = 0; q < 4; q++) acc[nt][q] = 0.f;
        }

        int rr = lane & 7;
        int g = lane >> 3;
        int a_row = wm * 16 + rr + (g & 1) * 8;
        int a_colg = (g >> 1) * 8;
        int b_krow = lane & 15;
        int b_ng = (lane >> 4) * 8;

        for (int k0 = 0; k0 < 512; k0 += 32) {
#pragma unroll
            for (int p = 0; p < 2; p++) {
                int idx = t + p * 256;
                int m = idx >> 3;
                int c4 = (idx & 7) * 4;
                float4 v = *(const float4*)&A[(size_t)(m0 + m) * 512 + k0 + c4];
                uint32_t h01, l01, h23, l23;
                split_pair(v.x, v.y, &h01, &l01);
                split_pair(v.z, v.w, &h23, &l23);
                int eo = m * 40 + c4;
                *(uint32_t*)&Ah[eo] = h01;
                *(uint32_t*)&Ah[eo + 2] = h23;
                *(uint32_t*)&Al[eo] = l01;
                *(uint32_t*)&Al[eo + 2] = l23;
            }
#pragma unroll
            for (int p = 0; p < 2; p++) {
                int idx = t + p * 256;
                int k = idx >> 4;
                int n4 = (idx & 15) * 4;
                float4 v = *(const float4*)&B[(size_t)(k0 + k) * 512 + n0 + n4];
                uint32_t h01, l01, h23, l23;
                split_pair(v.x, v.y, &h01, &l01);
                split_pair(v.z, v.w, &h23, &l23);
                int eo = k * 72 + n4;
                *(uint32_t*)&Bh[eo] = h01;
                *(uint32_t*)&Bh[eo + 2] = h23;
                *(uint32_t*)&Bl[eo] = l01;
                *(uint32_t*)&Bl[eo + 2] = l23;
            }
            __syncthreads();

#pragma unroll
            for (int ks = 0; ks < 32; ks += 16) {
                uint32_t ahi[4];
                uint32_t alo[4];
                uint32_t aoff = (uint32_t)((a_row * 40 + ks + a_colg) * 2);
                ldsm4p(ahi, ah_b + aoff);
                ldsm4p(alo, al_b + aoff);
#pragma unroll
                for (int nh = 0; nh < 2; nh++) {
                    uint32_t bhv[4];
                    uint32_t blv[4];
                    uint32_t boff = (uint32_t)(((ks + b_krow) * 72 + wn * 32 + nh * 16 + b_ng) * 2);
                    ldsm4t(bhv, bh_b + boff);
                    ldsm4t(blv, bl_b + boff);
                    mmabf(acc[nh * 2], ahi, bhv[0], bhv[1]);
                    mmabf(acc[nh * 2], ahi, blv[0], blv[1]);
                    mmabf(acc[nh * 2], alo, bhv[0], bhv[1]);
                    mmabf(acc[nh * 2 + 1], ahi, bhv[2], bhv[3]);
                    mmabf(acc[nh * 2 + 1], ahi, blv[2], blv[3]);
                    mmabf(acc[nh * 2 + 1], alo, bhv[2], bhv[3]);
                }
            }
            __syncthreads();
        }

        int r = lane >> 2;
        int cq = lane & 3;
#pragma unroll
        for (int nt = 0; nt < 4; nt++) {
            int col = n0 + wn * 32 + nt * 8 + 2 * cq;
            int row0 = m0 + wm * 16 + r;
            int row1 = row0 + 8;
            int hh = (col >> 6) & 7;
            int dd = col & 63;
            int b0i = row0 >> 10, i0 = row0 & 1023;
            int b1i = row1 >> 10, i1 = row1 & 1023;
            *(float2*)&C[(((size_t)(b0i * H + hh) * NPTS) + i0) * DH + dd] =
                make_float2(acc[nt][0], acc[nt][1]);
            *(float2*)&C[(((size_t)(b1i * H + hh) * NPTS) + i1) * DH + dd] =
                make_float2(acc[nt][2], acc[nt][3]);
        }
    } else if (bx < 1024) {
        // ---- KNN block ----
        int kb = bx - 768;
        __shared__ float sx[NPTS], sy[NPTS], sz[NPTS];
        int b = kb >> 7;
        int wid = t >> 5, lane = t & 31;
        for (int p = t; p < NPTS; p += 256) {
            sx[p] = canonical[(b * NPTS + p) * 3 + 0];
            sy[p] = canonical[(b * NPTS + p) * 3 + 1];
            sz[p] = canonical[(b * NPTS + p) * 3 + 2];
        }
        __syncthreads();
        int i = (kb & 127) * 8 + wid;
        float qx = sx[i], qy = sy[i], qz = sz[i];
        float prev_d = -1.f;
        int prev_j = -1;
        for (int s = 0; s < KNB; s++) {
            float bd = INFINITY;
            int bj = 1 << 30;
            for (int p = lane; p < NPTS; p += 32) {
                float dx = sx[p] - qx, dy = sy[p] - qy, dz = sz[p] - qz;
                float d2 = dx * dx + dy * dy + dz * dz;
                bool gt_prev = (d2 > prev_d) || (d2 == prev_d && p > prev_j);
                bool lt_best = (d2 < bd) || (d2 == bd && p < bj);
                if (gt_prev && lt_best) { bd = d2; bj = p; }
            }
#pragma unroll
            for (int off = 16; off; off >>= 1) {
                float od = __shfl_down_sync(0xFFFFFFFFu, bd, off);
                int   oj = __shfl_down_sync(0xFFFFFFFFu, bj, off);
                if (od < bd || (od == bd && oj < bj)) { bd = od; bj = oj; }
            }
            bd = __shfl_sync(0xFFFFFFFFu, bd, 0);
            bj = __shfl_sync(0xFFFFFFFFu, bj, 0);
            if (lane == 0) g_nbr[(b * NPTS + i) * KNB + s] = bj;
            prev_d = bd;
            prev_j = bj;
        }
    } else {
        // ---- wprep slice: 64 blocks = (h, seg) ----
        int wb = bx - 1024;
        int h = wb >> 3;
        int seg = wb & 7;
        for (int k = 0; k < 8; k++) {
            int idx = seg * 2048 + k * 256 + t;   // [0, 16384)
            int e = idx >> 6;
            int d = idx & 63;
            float v = aw1[(h * AINNER + e) * DH + d];
            __nv_bfloat16 hi = __float2bfloat16_rn(v);
            g_w1h[h * 256 * 72 + e * 72 + d] = hi;
            g_w1l[h * 256 * 72 + e * 72 + d] = __float2bfloat16_rn(v - __bfloat162float(hi));
        }
        for (int k = 0; k < 8; k++) {
            int idx = seg * 2048 + k * 256 + t;
            int d = idx >> 8;
            int e = idx & 255;
            float v = aw2[(h * DH + d) * AINNER + e];
            __nv_bfloat16 hi = __float2bfloat16_rn(v);
            g_w2h[h * 64 * 264 + d * 264 + e] = hi;
            g_w2l[h * 64 * 264 + d * 264 + e] = __float2bfloat16_rn(v - __bfloat162float(hi));
        }
    }
}

// ---------------- tensor-core GEMM (bf16x3) for output projection ----------------
__global__ void __launch_bounds__(256)
out_gemm(const float* __restrict__ A, const float* __restrict__ B,
         const float* __restrict__ bias, float* __restrict__ C) {
    __shared__ __nv_bfloat16 Ah[64 * 40];
    __shared__ __nv_bfloat16 Al[64 * 40];
    __shared__ __nv_bfloat16 Bh[32 * 72];
    __shared__ __nv_bfloat16 Bl[32 * 72];

    int t = threadIdx.x;
    int w = t >> 5;
    int lane = t & 31;
    int wm = w & 3;
    int wn = w >> 2;
    int m0 = blockIdx.y * 64;
    int n0 = blockIdx.x * 64;

    uint32_t ah_b = smem_u32(Ah);
    uint32_t al_b = smem_u32(Al);
    uint32_t bh_b = smem_u32(Bh);
    uint32_t bl_b = smem_u32(Bl);

    float acc[4][4];
#pragma unroll
    for (int nt = 0; nt < 4; nt++) {
#pragma unroll
        for (int q = 0; q < 4; q++) acc[nt][q] = 0.f;
    }

    int rr = lane & 7;
    int g = lane >> 3;
    int a_row = wm * 16 + rr + (g & 1) * 8;
    int a_colg = (g >> 1) * 8;
    int b_krow = lane & 15;
    int b_ng = (lane >> 4) * 8;

    for (int k0 = 0; k0 < 512; k0 += 32) {
#pragma unroll
        for (int p = 0; p < 2; p++) {
            int idx = t + p * 256;
            int m = idx >> 3;
            int c4 = (idx & 7) * 4;
            float4 v = *(const float4*)&A[(size_t)(m0 + m) * 512 + k0 + c4];
            uint32_t h01, l01, h23, l23;
            split_pair(v.x, v.y, &h01, &l01);
            split_pair(v.z, v.w, &h23, &l23);
            int eo = m * 40 + c4;
            *(uint32_t*)&Ah[eo] = h01;
            *(uint32_t*)&Ah[eo + 2] = h23;
            *(uint32_t*)&Al[eo] = l01;
            *(uint32_t*)&Al[eo + 2] = l23;
        }
#pragma unroll
        for (int p = 0; p < 2; p++) {
            int idx = t + p * 256;
            int k = idx >> 4;
            int n4 = (idx & 15) * 4;
            float4 v = *(const float4*)&B[(size_t)(k0 + k) * 512 + n0 + n4];
            uint32_t h01, l01, h23, l23;
            split_pair(v.x, v.y, &h01, &l01);
            split_pair(v.z, v.w, &h23, &l23);
            int eo = k * 72 + n4;
            *(uint32_t*)&Bh[eo] = h01;
            *(uint32_t*)&Bh[eo + 2] = h23;
            *(uint32_t*)&Bl[eo] = l01;
            *(uint32_t*)&Bl[eo + 2] = l23;
        }
        __syncthreads();

#pragma unroll
        for (int ks = 0; ks < 32; ks += 16) {
            uint32_t ahi[4];
            uint32_t alo[4];
            uint32_t aoff = (uint32_t)((a_row * 40 + ks + a_colg) * 2);
            ldsm4p(ahi, ah_b + aoff);
            ldsm4p(alo, al_b + aoff);
#pragma unroll
            for (int nh = 0; nh < 2; nh++) {
                uint32_t bhv[4];
                uint32_t blv[4];
                uint32_t boff = (uint32_t)(((ks + b_krow) * 72 + wn * 32 + nh * 16 + b_ng) * 2);
                ldsm4t(bhv, bh_b + boff);
                ldsm4t(blv, bl_b + boff);
                mmabf(acc[nh * 2], ahi, bhv[0], bhv[1]);
                mmabf(acc[nh * 2], ahi, blv[0], blv[1]);
                mmabf(acc[nh * 2], alo, bhv[0], bhv[1]);
                mmabf(acc[nh * 2 + 1], ahi, bhv[2], bhv[3]);
                mmabf(acc[nh * 2 + 1], ahi, blv[2], blv[3]);
                mmabf(acc[nh * 2 + 1], alo, bhv[2], bhv[3]);
            }
        }
        __syncthreads();
    }

    int r = lane >> 2;
    int cq = lane & 3;
#pragma unroll
    for (int nt = 0; nt < 4; nt++) {
        int col = n0 + wn * 32 + nt * 8 + 2 * cq;
        int row0 = m0 + wm * 16 + r;
        int row1 = row0 + 8;
        float bz0 = bias[col];
        float bz1 = bias[col + 1];
        *(float2*)&C[(size_t)row0 * 512 + col] = make_float2(acc[nt][0] + bz0, acc[nt][1] + bz1);
        *(float2*)&C[(size_t)row1 * 512 + col] = make_float2(acc[nt][2] + bz0, acc[nt][3] + bz1);
    }
}

// ---------------- rpe GEMM: B resident, 8 M-tiles per block. grid (8, 64). ----------------
__global__ void __launch_bounds__(256)
rpe_gemm(const float* __restrict__ A, const float* __restrict__ B,
         const float* __restrict__ bias, float* __restrict__ C) {
    __shared__ __nv_bfloat16 Bh[64 * 72];
    __shared__ __nv_bfloat16 Bl[64 * 72];
    __shared__ __nv_bfloat16 Ah[64 * 72];
    __shared__ __nv_bfloat16 Al[64 * 72];

    int t = threadIdx.x;
    int w = t >> 5;
    int lane = t & 31;
    int wm = w & 3;
    int wn = w >> 2;
    int n0 = blockIdx.x * 64;

    uint32_t ah_b = smem_u32(Ah);
    uint32_t al_b = smem_u32(Al);
    uint32_t bh_b = smem_u32(Bh);
    uint32_t bl_b = smem_u32(Bl);

#pragma unroll
    for (int p = 0; p < 4; p++) {
        int idx = t + p * 256;
        int k = idx >> 4;
        int n4 = (idx & 15) * 4;
        float4 v = *(const float4*)&B[(size_t)k * 512 + n0 + n4];
        uint32_t h01, l01, h23, l23;
        split_pair(v.x, v.y, &h01, &l01);
        split_pair(v.z, v.w, &h23, &l23);
        int eo = k * 72 + n4;
        *(uint32_t*)&Bh[eo] = h01;
        *(uint32_t*)&Bh[eo + 2] = h23;
        *(uint32_t*)&Bl[eo] = l01;
        *(uint32_t*)&Bl[eo + 2] = l23;
    }

    int rr = lane & 7;
    int g = lane >> 3;
    int a_row = wm * 16 + rr + (g & 1) * 8;
    int a_colg = (g >> 1) * 8;
    int b_krow = lane & 15;
    int b_ng = (lane >> 4) * 8;
    int r = lane >> 2;
    int cq = lane & 3;

    for (int mt = 0; mt < 8; mt++) {
        int m0 = (blockIdx.y * 8 + mt) * 64;
#pragma unroll
        for (int p = 0; p < 4; p++) {
            int idx = t + p * 256;
            int m = idx >> 4;
            int c4 = (idx & 15) * 4;
            float4 v = *(const float4*)&A[(size_t)(m0 + m) * 64 + c4];
            uint32_t h01, l01, h23, l23;
            split_pair(v.x, v.y, &h01, &l01);
            split_pair(v.z, v.w, &h23, &l23);
            int eo = m * 72 + c4;
            *(uint32_t*)&Ah[eo] = h01;
            *(uint32_t*)&Ah[eo + 2] = h23;
            *(uint32_t*)&Al[eo] = l01;
            *(uint32_t*)&Al[eo + 2] = l23;
        }
        __syncthreads();

        float acc[4][4];
#pragma unroll
        for (int nt = 0; nt < 4; nt++) {
#pragma unroll
            for (int q = 0; q < 4; q++) acc[nt][q] = 0.f;
        }

#pragma unroll
        for (int ks = 0; ks < 64; ks += 16) {
            uint32_t ahi[4];
            uint32_t alo[4];
            uint32_t aoff = (uint32_t)((a_row * 72 + ks + a_colg) * 2);
            ldsm4p(ahi, ah_b + aoff);
            ldsm4p(alo, al_b + aoff);
#pragma unroll
            for (int nh = 0; nh < 2; nh++) {
                uint32_t bhv[4];
                uint32_t blv[4];
                uint32_t boff = (uint32_t)(((ks + b_krow) * 72 + wn * 32 + nh * 16 + b_ng) * 2);
                ldsm4t(bhv, bh_b + boff);
                ldsm4t(blv, bl_b + boff);
                mmabf(acc[nh * 2], ahi, bhv[0], bhv[1]);
                mmabf(acc[nh * 2], ahi, blv[0], blv[1]);
                mmabf(acc[nh * 2], alo, bhv[0], bhv[1]);
                mmabf(acc[nh * 2 + 1], ahi, bhv[2], bhv[3]);
                mmabf(acc[nh * 2 + 1], ahi, blv[2], blv[3]);
                mmabf(acc[nh * 2 + 1], alo, bhv[2], bhv[3]);
            }
        }

#pragma unroll
        for (int nt = 0; nt < 4; nt++) {
            int col = n0 + wn * 32 + nt * 8 + 2 * cq;
            int row0 = m0 + wm * 16 + r;
            int row1 = row0 + 8;
            float bz0 = bias[col];
            float bz1 = bias[col + 1];
            *(float2*)&C[(size_t)row0 * 512 + col] = make_float2(acc[nt][0] + bz0, acc[nt][1] + bz1);
            *(float2*)&C[(size_t)row1 * 512 + col] = make_float2(acc[nt][2] + bz0, acc[nt][3] + bz1);
        }
        __syncthreads();
    }
}

// ---------------- RPE hidden layer ----------------
__global__ void __launch_bounds__(256)
h1_kernel(const float* __restrict__ canonical,
          const float* __restrict__ pw1, const float* __restrict__ pb1) {
    int bi = blockIdx.x;
    int b = bi >> 10;
    int t = threadIdx.x;
    __shared__ float relS[KNB][3];

    if (t < KNB) {
        int nv = g_nbr[bi * KNB + t];
#pragma unroll
        for (int c = 0; c < 3; c++) {
            relS[t][c] = canonical[(b * NPTS + nv) * 3 + c] - canonical[bi * 3 + c];
        }
    }
    __syncthreads();

    int e = t & 63;
    int j0 = (t >> 6) * 4;
    float w0 = pw1[e], w1 = pw1[64 + e], w2 = pw1[128 + e], bb = pb1[e];
#pragma unroll
    for (int jj = 0; jj < 4; jj++) {
        int j = j0 + jj;
        float a = relS[j][0] * w0 + relS[j][1] * w1 + relS[j][2] * w2 + bb;
        g_h1[(size_t)(bi * KNB + j) * POSH + e] = fmaxf(a, 0.f);
    }
}

// faithful replication of the reference's flattened-view gather
__device__ __forceinline__ int gather_row(int b, int h, int i, int j) {
    int m = 2 * i + (j >> 3);
    int ip = h * 128 + (m >> 4);
    int jp = m & 15;
    int nv = g_nbr[(b * NPTS + ip) * KNB + jp];
    int cc = nv * 8 + (j & 7);
    int h2 = cc >> 10;
    int i2 = cc & 1023;
    return ((b * H + h2) * NPTS + i2) * DH;
}

// smem layout (bytes) for attn
#define AT_W1H 0
#define AT_W1L 36864
#define AT_W2H 73728
#define AT_W2L 107520
#define AT_X   141312
#define AT_AB1 178176
#define AT_AB2 179200
#define AT_SMEM 179456

// warp-per-i tensor-core attn MLP (bf16x3) + softmax. 16 i per block, h uniform.
__global__ void __launch_bounds__(256, 1)
attn_tc_kernel(const float* __restrict__ ab1, const float* __restrict__ ab2) {
    extern __shared__ char smem[];
    uint32_t sb = smem_u32(smem);
    int t = threadIdx.x;
    int w = t >> 5;
    int lane = t & 31;
    int h = ((blockIdx.x * 16) >> 10) & 7;

    {
        const uint4* s1h = (const uint4*)&g_w1h[h * 256 * 72];
        const uint4* s1l = (const uint4*)&g_w1l[h * 256 * 72];
        uint4* d1h = (uint4*)(smem + AT_W1H);
        uint4* d1l = (uint4*)(smem + AT_W1L);
        for (int idx = t; idx < 256 * 72 / 8; idx += 256) {
            d1h[idx] = s1h[idx];
            d1l[idx] = s1l[idx];
        }
        const uint4* s2h = (const uint4*)&g_w2h[h * 64 * 264];
        const uint4* s2l = (const uint4*)&g_w2l[h * 64 * 264];
        uint4* d2h = (uint4*)(smem + AT_W2H);
        uint4* d2l = (uint4*)(smem + AT_W2L);
        for (int idx = t; idx < 64 * 264 / 8; idx += 256) {
            d2h[idx] = s2h[idx];
            d2l[idx] = s2l[idx];
        }
    }
    float* sab1 = (float*)(smem + AT_AB1);
    float* sab2 = (float*)(smem + AT_AB2);
    sab1[t] = ab1[h * AINNER + t];
    if (t < 64) sab2[t] = ab2[h * DH + t];
    __syncthreads();

    int r  = lane >> 2;
    int cq = lane & 3;
    int rr = lane & 7;
    int g  = lane >> 3;
    uint32_t xh_base = sb + AT_X + w * 4608;
    uint32_t xl_base = xh_base + 2304;
    char* xh_ptr = smem + AT_X + w * 4608;
    char* xl_ptr = xh_ptr + 2304;
    uint32_t w1h_base = sb + AT_W1H;
    uint32_t w1l_base = sb + AT_W1L;
    uint32_t w2h_base = sb + AT_W2H;
    uint32_t w2l_base = sb + AT_W2L;

    for (int l = 0; l < 2; l++) {
        int bhi = blockIdx.x * 16 + w * 2 + l;
        int i = bhi & 1023;
        int b = bhi >> 13;

        int sr = 0;
        if (lane < 16) sr = gather_row(b, h, i, lane);

#pragma unroll
        for (int it = 0; it < 8; it++) {
            int idx = lane + it * 32;
            int j  = idx >> 4;
            int d4 = idx & 15;
            int ro = __shfl_sync(0xFFFFFFFFu, sr, j) + d4 * 4;
            float4 qv = *(const float4*)&g_qh[ro];
            float4 kv = *(const float4*)&g_kh[ro];
            float4 rv = *(const float4*)&g_rpe[((size_t)(b * NPTS + i) * KNB + j) * INNER + h * DH + d4 * 4];
            uint32_t h01, l01, h23, l23;
            split_pair(qv.x - kv.x + rv.x, qv.y - kv.y + rv.y, &h01, &l01);
            split_pair(qv.z - kv.z + rv.z, qv.w - kv.w + rv.w, &h23, &l23);
            int off = j * 144 + d4 * 8;
            *(uint32_t*)(xh_ptr + off)     = h01;
            *(uint32_t*)(xh_ptr + off + 4) = h23;
            *(uint32_t*)(xl_ptr + off)     = l01;
            *(uint32_t*)(xl_ptr + off + 4) = l23;
        }
        __syncwarp();

        float acc2[8][4];
#pragma unroll
        for (int nt2 = 0; nt2 < 8; nt2++) {
            int d0 = nt2 * 8 + 2 * cq;
            acc2[nt2][0] = sab2[d0];
            acc2[nt2][1] = sab2[d0 + 1];
            acc2[nt2][2] = acc2[nt2][0];
            acc2[nt2][3] = acc2[nt2][1];
        }

#pragma unroll
        for (int half = 0; half < 2; half++) {
            float acc1[16][4];
#pragma unroll
            for (int nt = 0; nt < 16; nt++) {
                int e0 = (half * 16 + nt) * 8 + 2 * cq;
                acc1[nt][0] = sab1[e0];
                acc1[nt][1] = sab1[e0 + 1];
                acc1[nt][2] = acc1[nt][0];
                acc1[nt][3] = acc1[nt][1];
            }
#pragma unroll
            for (int kt = 0; kt < 4; kt++) {
                uint32_t ahi[4];
                uint32_t alo[4];
                uint32_t aoff = (uint32_t)((rr + (g & 1) * 8) * 144 + (kt * 16 + (g >> 1) * 8) * 2);
                ldsm4p(ahi, xh_base + aoff);
                ldsm4p(alo, xl_base + aoff);
#pragma unroll
                for (int ntp = 0; ntp < 8; ntp++) {
                    int erow = (half * 16 + 2 * ntp + (g >> 1)) * 8 + rr;
                    int dcol = kt * 16 + (g & 1) * 8;
                    uint32_t boff = (uint32_t)(erow * 144 + dcol * 2);
                    uint32_t bhv[4];
                    uint32_t blv[4];
                    ldsm4p(bhv, w1h_base + boff);
                    ldsm4p(blv, w1l_base + boff);
                    mmabf(acc1[2 * ntp], ahi, bhv[0], bhv[1]);
                    mmabf(acc1[2 * ntp], ahi, blv[0], blv[1]);
                    mmabf(acc1[2 * ntp], alo, bhv[0], bhv[1]);
                    mmabf(acc1[2 * ntp + 1], ahi, bhv[2], bhv[3]);
                    mmabf(acc1[2 * ntp + 1], ahi, blv[2], blv[3]);
                    mmabf(acc1[2 * ntp + 1], alo, bhv[2], bhv[3]);
                }
            }
#pragma unroll
            for (int ap = 0; ap < 8; ap++) {
                float v0 = fmaxf(acc1[2 * ap][0], 0.f);
                float v1 = fmaxf(acc1[2 * ap][1], 0.f);
                float v2 = fmaxf(acc1[2 * ap][2], 0.f);
                float v3 = fmaxf(acc1[2 * ap][3], 0.f);
                float v4 = fmaxf(acc1[2 * ap + 1][0], 0.f);
                float v5 = fmaxf(acc1[2 * ap + 1][1], 0.f);
                float v6 = fmaxf(acc1[2 * ap + 1][2], 0.f);
                float v7 = fmaxf(acc1[2 * ap + 1][3], 0.f);
                uint32_t a2h[4];
                uint32_t a2l[4];
                split_pair(v0, v1, &a2h[0], &a2l[0]);
                split_pair(v2, v3, &a2h[1], &a2l[1]);
                split_pair(v4, v5, &a2h[2], &a2l[2]);
                split_pair(v6, v7, &a2h[3], &a2l[3]);
                int kcol = (half * 8 + ap) * 16;
#pragma unroll
                for (int np = 0; np < 4; np++) {
                    int drow = (2 * np + (g >> 1)) * 8 + rr;
                    int ecol = kcol + (g & 1) * 8;
                    uint32_t b2off = (uint32_t)(drow * 528 + ecol * 2);
                    uint32_t b2h[4];
                    uint32_t b2l[4];
                    ldsm4p(b2h, w2h_base + b2off);
                    ldsm4p(b2l, w2l_base + b2off);
                    mmabf(acc2[2 * np], a2h, b2h[0], b2h[1]);
                    mmabf(acc2[2 * np], a2h, b2l[0], b2l[1]);
                    mmabf(acc2[2 * np], a2l, b2h[0], b2h[1]);
                    mmabf(acc2[2 * np + 1], a2h, b2h[2], b2h[3]);
                    mmabf(acc2[2 * np + 1], a2h, b2l[2], b2l[3]);
                    mmabf(acc2[2 * np + 1], a2l, b2h[2], b2h[3]);
                }
            }
        }

        size_t base = (size_t)bhi * KNB * DH;
#pragma unroll
        for (int nt2 = 0; nt2 < 8; nt2++) {
            float c0 = acc2[nt2][0];
            float c1 = acc2[nt2][1];
            float c2 = acc2[nt2][2];
            float c3 = acc2[nt2][3];
            float ma = fmaxf(c0, c2);
            float mb = fmaxf(c1, c3);
#pragma unroll
            for (int mk = 4; mk <= 16; mk <<= 1) {
                ma = fmaxf(ma, __shfl_xor_sync(0xFFFFFFFFu, ma, mk));
                mb = fmaxf(mb, __shfl_xor_sync(0xFFFFFFFFu, mb, mk));
            }
            float e0 = expf(c0 - ma);
            float e2 = expf(c2 - ma);
            float e1 = expf(c1 - mb);
            float e3 = expf(c3 - mb);
            float sa = e0 + e2;
            float sc = e1 + e3;
#pragma unroll
            for (int mk = 4; mk <= 16; mk <<= 1) {
                sa += __shfl_xor_sync(0xFFFFFFFFu, sa, mk);
                sc += __shfl_xor_sync(0xFFFFFFFFu, sc, mk);
            }
            float ia = 1.f / sa;
            float ic = 1.f / sc;
            int d0 = nt2 * 8 + 2 * cq;
            *(float2*)&g_attn[base + (size_t)r * DH + d0] = make_float2(e0 * ia, e1 * ic);
            *(float2*)&g_attn[base + (size_t)(r + 8) * DH + d0] = make_float2(e2 * ia, e3 * ic);
        }
        __syncwarp();
    }
}

// ---------------- norm over i (1024 threads: 16 partial sums of 64 i's) ----------------
__global__ void __launch_bounds__(1024)
norm_kernel() {
    int bhj = blockIdx.x;
    int j = bhj & 15;
    int bh = bhj >> 4;
    int t = threadIdx.x;
    int d = t & 63;
    int iq = t >> 6;       // 0..15
    size_t base = (size_t)bh * NPTS * KNB * DH + j * DH + d;
    float s = 0.f;
#pragma unroll 4
    for (int i = iq * 64; i < iq * 64 + 64; i++) {
        float v = g_attn[base + (size_t)i * KNB * DH];
        s += v * v;
    }
    __shared__ float rshared[16][64];
    rshared[iq][d] = s;
    __syncthreads();
    if (t < 64) {
        float acc = 0.f;
#pragma unroll
        for (int k = 0; k < 16; k++) acc += rshared[k][t];
        g_norm[bhj * DH + t] = sqrtf(acc);
    }
}

// ---------------- aggregate ----------------
__global__ void agg_kernel() {
    int t = threadIdx.x;
    int ii = t >> 6;
    int d = t & 63;
    int bhi = blockIdx.x * 4 + ii;
    int i = bhi & 1023;
    int h = (bhi >> 10) & 7;
    int b = bhi >> 13;

    __shared__ int srow[4][KNB];
    if (t < 64) {
        int i2 = t >> 4;
        int j = t & 15;
        srow[i2][j] = gather_row(b, h, (blockIdx.x * 4 + i2) & 1023, j);
    }
    __syncthreads();

    int bh = b * H + h;
    size_t abase = (size_t)bhi * KNB * DH + d;
    float acc = 0.f;
#pragma unroll
    for (int j = 0; j < KNB; j++) {
        float a = g_attn[abase + j * DH];
        float nm = g_norm[(bh * KNB + j) * DH + d];
        a /= fmaxf(nm, 1e-12f);
        float vg = g_vh[srow[ii][j] + d] +
                   g_rpe[(size_t)((b * NPTS + i) * KNB + j) * INNER + h * DH + d];
        acc = fmaf(a, vg, acc);
    }
    g_agg[(b * NPTS + i) * INNER + h * DH + d] = acc;
}

// ---------------- launch ----------------
extern "C" void kernel_launch(void* const* d_in, const int* in_sizes, int n_in,
                              void* d_out, int out_size) {
    const float* query     = (const float*)d_in[0];
    const float* key_in    = (const float*)d_in[1];
    const float* value     = (const float*)d_in[2];
    const float* canonical = (const float*)d_in[3];
    const float* w_q       = (const float*)d_in[4];
    const float* w_k       = (const float*)d_in[5];
    const float* w_v       = (const float*)d_in[6];
    const float* w_out     = (const float*)d_in[7];
    const float* b_out     = (const float*)d_in[8];
    const float* pos_w1    = (const float*)d_in[9];
    const float* pos_b1    = (const float*)d_in[10];
    const float* pos_w2    = (const float*)d_in[11];
    const float* pos_b2    = (const float*)d_in[12];
    const float* aw1       = (const float*)d_in[13];
    const float* ab1       = (const float*)d_in[14];
    const float* aw2       = (const float*)d_in[15];
    const float* ab2       = (const float*)d_in[16];
    float* out = (float*)d_out;

    float* h1;  cudaGetSymbolAddress((void**)&h1,  g_h1);
    float* rpe; cudaGetSymbolAddress((void**)&rpe, g_rpe);
    float* agg; cudaGetSymbolAddress((void**)&agg, g_agg);

    cudaFuncSetAttribute(attn_tc_kernel,
                         cudaFuncAttributeMaxDynamicSharedMemorySize, AT_SMEM);

    // fused prologue: proj + knn + wprep (independent work, one wave)
    pre_kernel<<<1088, 256>>>(query, w_q, key_in, w_k, value, w_v,
                              canonical, aw1, aw2);

    h1_kernel<<<BS * NPTS, 256>>>(canonical, pos_w1, pos_b1);

    dim3 rgrid(8, 64);
    rpe_gemm<<<rgrid, 256>>>(h1, pos_w2, pos_b2, rpe);

    attn_tc_kernel<<<BS * H * NPTS / 16, 256, AT_SMEM>>>(ab1, ab2);
    norm_kernel<<<BS * H * KNB, 1024>>>();
    agg_kernel<<<BS * H * NPTS / 4, 256>>>();

    dim3 ogrid(8, 32, 1);
    out_gemm<<<ogrid, 256>>>(agg, w_out, b_out, out);
}

// round 15
// speedup vs baseline: 1.0319x; 1.0183x over previous
#include <cuda_runtime.h>
#include <cuda_bf16.h>
#include <cstdint>
#include <cstring>
#include <math.h>

// Problem constants
#define BS 2
#define NPTS 1024
#define H 8
#define DH 64
#define KNB 16
#define EMB 512
#define INNER 512
#define AINNER 256
#define POSH 64

// ---------------- scratch (static device globals; no allocation) ----------------
__device__ float g_qh[BS * H * NPTS * DH];
__device__ float g_kh[BS * H * NPTS * DH];
__device__ float g_vh[BS * H * NPTS * DH];
__device__ int   g_nbr[BS * NPTS * KNB];
__device__ float g_h1[BS * NPTS * KNB * POSH];
__device__ float g_rpe[BS * NPTS * KNB * INNER];
__device__ float g_attn[BS * H * NPTS * KNB * DH];
__device__ float g_norm[BS * H * KNB * DH];
__device__ float g_agg[BS * NPTS * INNER];
// precomputed per-head attn weight planes (layouts match attn smem)
__device__ __nv_bfloat16 g_w1h[H * 256 * 72];
__device__ __nv_bfloat16 g_w1l[H * 256 * 72];
__device__ __nv_bfloat16 g_w2h[H * 64 * 264];
__device__ __nv_bfloat16 g_w2l[H * 64 * 264];

// ---------------- shared helpers ----------------
__device__ __forceinline__ uint32_t smem_u32(const void* p) {
    uint32_t a;
    asm("{ .reg .u64 tmp; cvta.to.shared.u64 tmp, %1; cvt.u32.u64 %0, tmp; }"
        : "=r"(a) : "l"(p));
    return a;
}

__device__ __forceinline__ void ldsm4p(uint32_t* r, uint32_t addr) {
    asm volatile("ldmatrix.sync.aligned.m8n8.x4.shared.b16 {%0,%1,%2,%3}, [%4];"
                 : "=r"(r[0]), "=r"(r[1]), "=r"(r[2]), "=r"(r[3])
                 : "r"(addr));
}

__device__ __forceinline__ void ldsm4t(uint32_t* r, uint32_t addr) {
    asm volatile("ldmatrix.sync.aligned.m8n8.x4.trans.shared.b16 {%0,%1,%2,%3}, [%4];"
                 : "=r"(r[0]), "=r"(r[1]), "=r"(r[2]), "=r"(r[3])
                 : "r"(addr));
}

__device__ __forceinline__ void mmabf(float* c, const uint32_t* a, uint32_t b0, uint32_t b1) {
    asm volatile("mma.sync.aligned.m16n8k16.row.col.f32.bf16.bf16.f32 "
                 "{%0,%1,%2,%3}, {%4,%5,%6,%7}, {%8,%9}, {%0,%1,%2,%3};"
                 : "+f"(c[0]), "+f"(c[1]), "+f"(c[2]), "+f"(c[3])
                 : "r"(a[0]), "r"(a[1]), "r"(a[2]), "r"(a[3]), "r"(b0), "r"(b1));
}

__device__ __forceinline__ void split_pair(float v0, float v1, uint32_t* hi, uint32_t* lo) {
    __nv_bfloat162 hv = __floats2bfloat162_rn(v0, v1);
    float f0 = __low2float(hv);
    float f1 = __high2float(hv);
    __nv_bfloat162 lv = __floats2bfloat162_rn(v0 - f0, v1 - f1);
    uint32_t uh, ul;
    memcpy(&uh, &hv, 4);
    memcpy(&ul, &lv, 4);
    *hi = uh;
    *lo = ul;
}

// 6-mma compensated pair, interleaved: chain distance 2 per accumulator,
// per-accumulator op order (hi.bh, hi.bl, lo.bh) unchanged -> bitwise identical.
__device__ __forceinline__ void mma6(float* ce, float* co,
                                     const uint32_t* ahi, const uint32_t* alo,
                                     const uint32_t* bh, const uint32_t* bl) {
    mmabf(ce, ahi, bh[0], bh[1]);
    mmabf(co, ahi, bh[2], bh[3]);
    mmabf(ce, ahi, bl[0], bl[1]);
    mmabf(co, ahi, bl[2], bl[3]);
    mmabf(ce, alo, bh[0], bh[1]);
    mmabf(co, alo, bh[2], bh[3]);
}

// ---------------- fused prologue: proj GEMMs + KNN + wprep ----------------
// grid.x partition: [0,768) proj (n=8, m=32, z=3); [768,1024) knn; [1024,1088) wprep
__global__ void __launch_bounds__(256)
pre_kernel(const float* __restrict__ query, const float* __restrict__ w_q,
           const float* __restrict__ key_in, const float* __restrict__ w_k,
           const float* __restrict__ value, const float* __restrict__ w_v,
           const float* __restrict__ canonical,
           const float* __restrict__ aw1, const float* __restrict__ aw2) {
    int bx = blockIdx.x;
    int t = threadIdx.x;

    if (bx < 768) {
        // ---- projection GEMM tile ----
        int z = bx >> 8;
        int rem = bx & 255;
        int n0 = (rem & 7) * 64;
        int m0 = (rem >> 3) * 64;
        const float* A = (z == 0) ? query : (z == 1) ? key_in : value;
        const float* B = (z == 0) ? w_q : (z == 1) ? w_k : w_v;
        float* C = (z == 0) ? g_qh : (z == 1) ? g_kh : g_vh;

        __shared__ __nv_bfloat16 Ah[64 * 40];
        __shared__ __nv_bfloat16 Al[64 * 40];
        __shared__ __nv_bfloat16 Bh[32 * 72];
        __shared__ __nv_bfloat16 Bl[32 * 72];

        int w = t >> 5;
        int lane = t & 31;
        int wm = w & 3;
        int wn = w >> 2;
        uint32_t ah_b = smem_u32(Ah);
        uint32_t al_b = smem_u32(Al);
        uint32_t bh_b = smem_u32(Bh);
        uint32_t bl_b = smem_u32(Bl);

        float acc[4][4];
#pragma unroll
        for (int nt = 0; nt < 4; nt++) {
#pragma unroll
            for (int q = 0; q < 4; q++) acc[nt][q] = 0.f;
        }

        int rr = lane & 7;
        int g = lane >> 3;
        int a_row = wm * 16 + rr + (g & 1) * 8;
        int a_colg = (g >> 1) * 8;
        int b_krow = lane & 15;
        int b_ng = (lane >> 4) * 8;

        for (int k0 = 0; k0 < 512; k0 += 32) {
#pragma unroll
            for (int p = 0; p < 2; p++) {
                int idx = t + p * 256;
                int m = idx >> 3;
                int c4 = (idx & 7) * 4;
                float4 v = *(const float4*)&A[(size_t)(m0 + m) * 512 + k0 + c4];
                uint32_t h01, l01, h23, l23;
                split_pair(v.x, v.y, &h01, &l01);
                split_pair(v.z, v.w, &h23, &l23);
                int eo = m * 40 + c4;
                *(uint32_t*)&Ah[eo] = h01;
                *(uint32_t*)&Ah[eo + 2] = h23;
                *(uint32_t*)&Al[eo] = l01;
                *(uint32_t*)&Al[eo + 2] = l23;
            }
#pragma unroll
            for (int p = 0; p < 2; p++) {
                int idx = t + p * 256;
                int k = idx >> 4;
                int n4 = (idx & 15) * 4;
                float4 v = *(const float4*)&B[(size_t)(k0 + k) * 512 + n0 + n4];
                uint32_t h01, l01, h23, l23;
                split_pair(v.x, v.y, &h01, &l01);
                split_pair(v.z, v.w, &h23, &l23);
                int eo = k * 72 + n4;
                *(uint32_t*)&Bh[eo] = h01;
                *(uint32_t*)&Bh[eo + 2] = h23;
                *(uint32_t*)&Bl[eo] = l01;
                *(uint32_t*)&Bl[eo + 2] = l23;
            }
            __syncthreads();

#pragma unroll
            for (int ks = 0; ks < 32; ks += 16) {
                uint32_t ahi[4];
                uint32_t alo[4];
                uint32_t aoff = (uint32_t)((a_row * 40 + ks + a_colg) * 2);
                ldsm4p(ahi, ah_b + aoff);
                ldsm4p(alo, al_b + aoff);
#pragma unroll
                for (int nh = 0; nh < 2; nh++) {
                    uint32_t bhv[4];
                    uint32_t blv[4];
                    uint32_t boff = (uint32_t)(((ks + b_krow) * 72 + wn * 32 + nh * 16 + b_ng) * 2);
                    ldsm4t(bhv, bh_b + boff);
                    ldsm4t(blv, bl_b + boff);
                    mma6(acc[nh * 2], acc[nh * 2 + 1], ahi, alo, bhv, blv);
                }
            }
            __syncthreads();
        }

        int r = lane >> 2;
        int cq = lane & 3;
#pragma unroll
        for (int nt = 0; nt < 4; nt++) {
            int col = n0 + wn * 32 + nt * 8 + 2 * cq;
            int row0 = m0 + wm * 16 + r;
            int row1 = row0 + 8;
            int hh = (col >> 6) & 7;
            int dd = col & 63;
            int b0i = row0 >> 10, i0 = row0 & 1023;
            int b1i = row1 >> 10, i1 = row1 & 1023;
            *(float2*)&C[(((size_t)(b0i * H + hh) * NPTS) + i0) * DH + dd] =
                make_float2(acc[nt][0], acc[nt][1]);
            *(float2*)&C[(((size_t)(b1i * H + hh) * NPTS) + i1) * DH + dd] =
                make_float2(acc[nt][2], acc[nt][3]);
        }
    } else if (bx < 1024) {
        // ---- KNN block ----
        int kb = bx - 768;
        __shared__ float sx[NPTS], sy[NPTS], sz[NPTS];
        int b = kb >> 7;
        int wid = t >> 5, lane = t & 31;
        for (int p = t; p < NPTS; p += 256) {
            sx[p] = canonical[(b * NPTS + p) * 3 + 0];
            sy[p] = canonical[(b * NPTS + p) * 3 + 1];
            sz[p] = canonical[(b * NPTS + p) * 3 + 2];
        }
        __syncthreads();
        int i = (kb & 127) * 8 + wid;
        float qx = sx[i], qy = sy[i], qz = sz[i];
        float prev_d = -1.f;
        int prev_j = -1;
        for (int s = 0; s < KNB; s++) {
            float bd = INFINITY;
            int bj = 1 << 30;
            for (int p = lane; p < NPTS; p += 32) {
                float dx = sx[p] - qx, dy = sy[p] - qy, dz = sz[p] - qz;
                float d2 = dx * dx + dy * dy + dz * dz;
                bool gt_prev = (d2 > prev_d) || (d2 == prev_d && p > prev_j);
                bool lt_best = (d2 < bd) || (d2 == bd && p < bj);
                if (gt_prev && lt_best) { bd = d2; bj = p; }
            }
#pragma unroll
            for (int off = 16; off; off >>= 1) {
                float od = __shfl_down_sync(0xFFFFFFFFu, bd, off);
                int   oj = __shfl_down_sync(0xFFFFFFFFu, bj, off);
                if (od < bd || (od == bd && oj < bj)) { bd = od; bj = oj; }
            }
            bd = __shfl_sync(0xFFFFFFFFu, bd, 0);
            bj = __shfl_sync(0xFFFFFFFFu, bj, 0);
            if (lane == 0) g_nbr[(b * NPTS + i) * KNB + s] = bj;
            prev_d = bd;
            prev_j = bj;
        }
    } else {
        // ---- wprep slice: 64 blocks = (h, seg) ----
        int wb = bx - 1024;
        int h = wb >> 3;
        int seg = wb & 7;
        for (int k = 0; k < 8; k++) {
            int idx = seg * 2048 + k * 256 + t;   // [0, 16384)
            int e = idx >> 6;
            int d = idx & 63;
            float v = aw1[(h * AINNER + e) * DH + d];
            __nv_bfloat16 hi = __float2bfloat16_rn(v);
            g_w1h[h * 256 * 72 + e * 72 + d] = hi;
            g_w1l[h * 256 * 72 + e * 72 + d] = __float2bfloat16_rn(v - __bfloat162float(hi));
        }
        for (int k = 0; k < 8; k++) {
            int idx = seg * 2048 + k * 256 + t;
            int d = idx >> 8;
            int e = idx & 255;
            float v = aw2[(h * DH + d) * AINNER + e];
            __nv_bfloat16 hi = __float2bfloat16_rn(v);
            g_w2h[h * 64 * 264 + d * 264 + e] = hi;
            g_w2l[h * 64 * 264 + d * 264 + e] = __float2bfloat16_rn(v - __bfloat162float(hi));
        }
    }
}

// ---------------- tensor-core GEMM (bf16x3) for output projection ----------------
__global__ void __launch_bounds__(256)
out_gemm(const float* __restrict__ A, const float* __restrict__ B,
         const float* __restrict__ bias, float* __restrict__ C) {
    __shared__ __nv_bfloat16 Ah[64 * 40];
    __shared__ __nv_bfloat16 Al[64 * 40];
    __shared__ __nv_bfloat16 Bh[32 * 72];
    __shared__ __nv_bfloat16 Bl[32 * 72];

    int t = threadIdx.x;
    int w = t >> 5;
    int lane = t & 31;
    int wm = w & 3;
    int wn = w >> 2;
    int m0 = blockIdx.y * 64;
    int n0 = blockIdx.x * 64;

    uint32_t ah_b = smem_u32(Ah);
    uint32_t al_b = smem_u32(Al);
    uint32_t bh_b = smem_u32(Bh);
    uint32_t bl_b = smem_u32(Bl);

    float acc[4][4];
#pragma unroll
    for (int nt = 0; nt < 4; nt++) {
#pragma unroll
        for (int q = 0; q < 4; q++) acc[nt][q] = 0.f;
    }

    int rr = lane & 7;
    int g = lane >> 3;
    int a_row = wm * 16 + rr + (g & 1) * 8;
    int a_colg = (g >> 1) * 8;
    int b_krow = lane & 15;
    int b_ng = (lane >> 4) * 8;

    for (int k0 = 0; k0 < 512; k0 += 32) {
#pragma unroll
        for (int p = 0; p < 2; p++) {
            int idx = t + p * 256;
            int m = idx >> 3;
            int c4 = (idx & 7) * 4;
            float4 v = *(const float4*)&A[(size_t)(m0 + m) * 512 + k0 + c4];
            uint32_t h01, l01, h23, l23;
            split_pair(v.x, v.y, &h01, &l01);
            split_pair(v.z, v.w, &h23, &l23);
            int eo = m * 40 + c4;
            *(uint32_t*)&Ah[eo] = h01;
            *(uint32_t*)&Ah[eo + 2] = h23;
            *(uint32_t*)&Al[eo] = l01;
            *(uint32_t*)&Al[eo + 2] = l23;
        }
#pragma unroll
        for (int p = 0; p < 2; p++) {
            int idx = t + p * 256;
            int k = idx >> 4;
            int n4 = (idx & 15) * 4;
            float4 v = *(const float4*)&B[(size_t)(k0 + k) * 512 + n0 + n4];
            uint32_t h01, l01, h23, l23;
            split_pair(v.x, v.y, &h01, &l01);
            split_pair(v.z, v.w, &h23, &l23);
            int eo = k * 72 + n4;
            *(uint32_t*)&Bh[eo] = h01;
            *(uint32_t*)&Bh[eo + 2] = h23;
            *(uint32_t*)&Bl[eo] = l01;
            *(uint32_t*)&Bl[eo + 2] = l23;
        }
        __syncthreads();

#pragma unroll
        for (int ks = 0; ks < 32; ks += 16) {
            uint32_t ahi[4];
            uint32_t alo[4];
            uint32_t aoff = (uint32_t)((a_row * 40 + ks + a_colg) * 2);
            ldsm4p(ahi, ah_b + aoff);
            ldsm4p(alo, al_b + aoff);
#pragma unroll
            for (int nh = 0; nh < 2; nh++) {
                uint32_t bhv[4];
                uint32_t blv[4];
                uint32_t boff = (uint32_t)(((ks + b_krow) * 72 + wn * 32 + nh * 16 + b_ng) * 2);
                ldsm4t(bhv, bh_b + boff);
                ldsm4t(blv, bl_b + boff);
                mma6(acc[nh * 2], acc[nh * 2 + 1], ahi, alo, bhv, blv);
            }
        }
        __syncthreads();
    }

    int r = lane >> 2;
    int cq = lane & 3;
#pragma unroll
    for (int nt = 0; nt < 4; nt++) {
        int col = n0 + wn * 32 + nt * 8 + 2 * cq;
        int row0 = m0 + wm * 16 + r;
        int row1 = row0 + 8;
        float bz0 = bias[col];
        float bz1 = bias[col + 1];
        *(float2*)&C[(size_t)row0 * 512 + col] = make_float2(acc[nt][0] + bz0, acc[nt][1] + bz1);
        *(float2*)&C[(size_t)row1 * 512 + col] = make_float2(acc[nt][2] + bz0, acc[nt][3] + bz1);
    }
}

// ---------------- rpe GEMM: B resident, 8 M-tiles per block. grid (8, 64). ----------------
__global__ void __launch_bounds__(256)
rpe_gemm(const float* __restrict__ A, const float* __restrict__ B,
         const float* __restrict__ bias, float* __restrict__ C) {
    __shared__ __nv_bfloat16 Bh[64 * 72];
    __shared__ __nv_bfloat16 Bl[64 * 72];
    __shared__ __nv_bfloat16 Ah[64 * 72];
    __shared__ __nv_bfloat16 Al[64 * 72];

    int t = threadIdx.x;
    int w = t >> 5;
    int lane = t & 31;
    int wm = w & 3;
    int wn = w >> 2;
    int n0 = blockIdx.x * 64;

    uint32_t ah_b = smem_u32(Ah);
    uint32_t al_b = smem_u32(Al);
    uint32_t bh_b = smem_u32(Bh);
    uint32_t bl_b = smem_u32(Bl);

#pragma unroll
    for (int p = 0; p < 4; p++) {
        int idx = t + p * 256;
        int k = idx >> 4;
        int n4 = (idx & 15) * 4;
        float4 v = *(const float4*)&B[(size_t)k * 512 + n0 + n4];
        uint32_t h01, l01, h23, l23;
        split_pair(v.x, v.y, &h01, &l01);
        split_pair(v.z, v.w, &h23, &l23);
        int eo = k * 72 + n4;
        *(uint32_t*)&Bh[eo] = h01;
        *(uint32_t*)&Bh[eo + 2] = h23;
        *(uint32_t*)&Bl[eo] = l01;
        *(uint32_t*)&Bl[eo + 2] = l23;
    }

    int rr = lane & 7;
    int g = lane >> 3;
    int a_row = wm * 16 + rr + (g & 1) * 8;
    int a_colg = (g >> 1) * 8;
    int b_krow = lane & 15;
    int b_ng = (lane >> 4) * 8;
    int r = lane >> 2;
    int cq = lane & 3;

    for (int mt = 0; mt < 8; mt++) {
        int m0 = (blockIdx.y * 8 + mt) * 64;
#pragma unroll
        for (int p = 0; p < 4; p++) {
            int idx = t + p * 256;
            int m = idx >> 4;
            int c4 = (idx & 15) * 4;
            float4 v = *(const float4*)&A[(size_t)(m0 + m) * 64 + c4];
            uint32_t h01, l01, h23, l23;
            split_pair(v.x, v.y, &h01, &l01);
            split_pair(v.z, v.w, &h23, &l23);
            int eo = m * 72 + c4;
            *(uint32_t*)&Ah[eo] = h01;
            *(uint32_t*)&Ah[eo + 2] = h23;
            *(uint32_t*)&Al[eo] = l01;
            *(uint32_t*)&Al[eo + 2] = l23;
        }
        __syncthreads();

        float acc[4][4];
#pragma unroll
        for (int nt = 0; nt < 4; nt++) {
#pragma unroll
            for (int q = 0; q < 4; q++) acc[nt][q] = 0.f;
        }

#pragma unroll
        for (int ks = 0; ks < 64; ks += 16) {
            uint32_t ahi[4];
            uint32_t alo[4];
            uint32_t aoff = (uint32_t)((a_row * 72 + ks + a_colg) * 2);
            ldsm4p(ahi, ah_b + aoff);
            ldsm4p(alo, al_b + aoff);
#pragma unroll
            for (int nh = 0; nh < 2; nh++) {
                uint32_t bhv[4];
                uint32_t blv[4];
                uint32_t boff = (uint32_t)(((ks + b_krow) * 72 + wn * 32 + nh * 16 + b_ng) * 2);
                ldsm4t(bhv, bh_b + boff);
                ldsm4t(blv, bl_b + boff);
                mma6(acc[nh * 2], acc[nh * 2 + 1], ahi, alo, bhv, blv);
            }
        }

#pragma unroll
        for (int nt = 0; nt < 4; nt++) {
            int col = n0 + wn * 32 + nt * 8 + 2 * cq;
            int row0 = m0 + wm * 16 + r;
            int row1 = row0 + 8;
            float bz0 = bias[col];
            float bz1 = bias[col + 1];
            *(float2*)&C[(size_t)row0 * 512 + col] = make_float2(acc[nt][0] + bz0, acc[nt][1] + bz1);
            *(float2*)&C[(size_t)row1 * 512 + col] = make_float2(acc[nt][2] + bz0, acc[nt][3] + bz1);
        }
        __syncthreads();
    }
}

// ---------------- RPE hidden layer ----------------
__global__ void __launch_bounds__(256)
h1_kernel(const float* __restrict__ canonical,
          const float* __restrict__ pw1, const float* __restrict__ pb1) {
    int bi = blockIdx.x;
    int b = bi >> 10;
    int t = threadIdx.x;
    __shared__ float relS[KNB][3];

    if (t < KNB) {
        int nv = g_nbr[bi * KNB + t];
#pragma unroll
        for (int c = 0; c < 3; c++) {
            relS[t][c] = canonical[(b * NPTS + nv) * 3 + c] - canonical[bi * 3 + c];
        }
    }
    __syncthreads();

    int e = t & 63;
    int j0 = (t >> 6) * 4;
    float w0 = pw1[e], w1 = pw1[64 + e], w2 = pw1[128 + e], bb = pb1[e];
#pragma unroll
    for (int jj = 0; jj < 4; jj++) {
        int j = j0 + jj;
        float a = relS[j][0] * w0 + relS[j][1] * w1 + relS[j][2] * w2 + bb;
        g_h1[(size_t)(bi * KNB + j) * POSH + e] = fmaxf(a, 0.f);
    }
}

// faithful replication of the reference's flattened-view gather
__device__ __forceinline__ int gather_row(int b, int h, int i, int j) {
    int m = 2 * i + (j >> 3);
    int ip = h * 128 + (m >> 4);
    int jp = m & 15;
    int nv = g_nbr[(b * NPTS + ip) * KNB + jp];
    int cc = nv * 8 + (j & 7);
    int h2 = cc >> 10;
    int i2 = cc & 1023;
    return ((b * H + h2) * NPTS + i2) * DH;
}

// smem layout (bytes) for attn
#define AT_W1H 0
#define AT_W1L 36864
#define AT_W2H 73728
#define AT_W2L 107520
#define AT_X   141312
#define AT_AB1 178176
#define AT_AB2 179200
#define AT_SMEM 179456

// warp-per-i tensor-core attn MLP (bf16x3) + softmax. 16 i per block, h uniform.
__global__ void __launch_bounds__(256, 1)
attn_tc_kernel(const float* __restrict__ ab1, const float* __restrict__ ab2) {
    extern __shared__ char smem[];
    uint32_t sb = smem_u32(smem);
    int t = threadIdx.x;
    int w = t >> 5;
    int lane = t & 31;
    int h = ((blockIdx.x * 16) >> 10) & 7;

    {
        const uint4* s1h = (const uint4*)&g_w1h[h * 256 * 72];
        const uint4* s1l = (const uint4*)&g_w1l[h * 256 * 72];
        uint4* d1h = (uint4*)(smem + AT_W1H);
        uint4* d1l = (uint4*)(smem + AT_W1L);
        for (int idx = t; idx < 256 * 72 / 8; idx += 256) {
            d1h[idx] = s1h[idx];
            d1l[idx] = s1l[idx];
        }
        const uint4* s2h = (const uint4*)&g_w2h[h * 64 * 264];
        const uint4* s2l = (const uint4*)&g_w2l[h * 64 * 264];
        uint4* d2h = (uint4*)(smem + AT_W2H);
        uint4* d2l = (uint4*)(smem + AT_W2L);
        for (int idx = t; idx < 64 * 264 / 8; idx += 256) {
            d2h[idx] = s2h[idx];
            d2l[idx] = s2l[idx];
        }
    }
    float* sab1 = (float*)(smem + AT_AB1);
    float* sab2 = (float*)(smem + AT_AB2);
    sab1[t] = ab1[h * AINNER + t];
    if (t < 64) sab2[t] = ab2[h * DH + t];
    __syncthreads();

    int r  = lane >> 2;
    int cq = lane & 3;
    int rr = lane & 7;
    int g  = lane >> 3;
    uint32_t xh_base = sb + AT_X + w * 4608;
    uint32_t xl_base = xh_base + 2304;
    char* xh_ptr = smem + AT_X + w * 4608;
    char* xl_ptr = xh_ptr + 2304;
    uint32_t w1h_base = sb + AT_W1H;
    uint32_t w1l_base = sb + AT_W1L;
    uint32_t w2h_base = sb + AT_W2H;
    uint32_t w2l_base = sb + AT_W2L;

    for (int l = 0; l < 2; l++) {
        int bhi = blockIdx.x * 16 + w * 2 + l;
        int i = bhi & 1023;
        int b = bhi >> 13;

        int sr = 0;
        if (lane < 16) sr = gather_row(b, h, i, lane);

#pragma unroll
        for (int it = 0; it < 8; it++) {
            int idx = lane + it * 32;
            int j  = idx >> 4;
            int d4 = idx & 15;
            int ro = __shfl_sync(0xFFFFFFFFu, sr, j) + d4 * 4;
            float4 qv = *(const float4*)&g_qh[ro];
            float4 kv = *(const float4*)&g_kh[ro];
            float4 rv = *(const float4*)&g_rpe[((size_t)(b * NPTS + i) * KNB + j) * INNER + h * DH + d4 * 4];
            uint32_t h01, l01, h23, l23;
            split_pair(qv.x - kv.x + rv.x, qv.y - kv.y + rv.y, &h01, &l01);
            split_pair(qv.z - kv.z + rv.z, qv.w - kv.w + rv.w, &h23, &l23);
            int off = j * 144 + d4 * 8;
            *(uint32_t*)(xh_ptr + off)     = h01;
            *(uint32_t*)(xh_ptr + off + 4) = h23;
            *(uint32_t*)(xl_ptr + off)     = l01;
            *(uint32_t*)(xl_ptr + off + 4) = l23;
        }
        __syncwarp();

        float acc2[8][4];
#pragma unroll
        for (int nt2 = 0; nt2 < 8; nt2++) {
            int d0 = nt2 * 8 + 2 * cq;
            acc2[nt2][0] = sab2[d0];
            acc2[nt2][1] = sab2[d0 + 1];
            acc2[nt2][2] = acc2[nt2][0];
            acc2[nt2][3] = acc2[nt2][1];
        }

#pragma unroll
        for (int half = 0; half < 2; half++) {
            float acc1[16][4];
#pragma unroll
            for (int nt = 0; nt < 16; nt++) {
                int e0 = (half * 16 + nt) * 8 + 2 * cq;
                acc1[nt][0] = sab1[e0];
                acc1[nt][1] = sab1[e0 + 1];
                acc1[nt][2] = acc1[nt][0];
                acc1[nt][3] = acc1[nt][1];
            }
#pragma unroll
            for (int kt = 0; kt < 4; kt++) {
                uint32_t ahi[4];
                uint32_t alo[4];
                uint32_t aoff = (uint32_t)((rr + (g & 1) * 8) * 144 + (kt * 16 + (g >> 1) * 8) * 2);
                ldsm4p(ahi, xh_base + aoff);
                ldsm4p(alo, xl_base + aoff);
#pragma unroll
                for (int ntp = 0; ntp < 8; ntp++) {
                    int erow = (half * 16 + 2 * ntp + (g >> 1)) * 8 + rr;
                    int dcol = kt * 16 + (g & 1) * 8;
                    uint32_t boff = (uint32_t)(erow * 144 + dcol * 2);
                    uint32_t bhv[4];
                    uint32_t blv[4];
                    ldsm4p(bhv, w1h_base + boff);
                    ldsm4p(blv, w1l_base + boff);
                    mma6(acc1[2 * ntp], acc1[2 * ntp + 1], ahi, alo, bhv, blv);
                }
            }
#pragma unroll
            for (int ap = 0; ap < 8; ap++) {
                float v0 = fmaxf(acc1[2 * ap][0], 0.f);
                float v1 = fmaxf(acc1[2 * ap][1], 0.f);
                float v2 = fmaxf(acc1[2 * ap][2], 0.f);
                float v3 = fmaxf(acc1[2 * ap][3], 0.f);
                float v4 = fmaxf(acc1[2 * ap + 1][0], 0.f);
                float v5 = fmaxf(acc1[2 * ap + 1][1], 0.f);
                float v6 = fmaxf(acc1[2 * ap + 1][2], 0.f);
                float v7 = fmaxf(acc1[2 * ap + 1][3], 0.f);
                uint32_t a2h[4];
                uint32_t a2l[4];
                split_pair(v0, v1, &a2h[0], &a2l[0]);
                split_pair(v2, v3, &a2h[1], &a2l[1]);
                split_pair(v4, v5, &a2h[2], &a2l[2]);
                split_pair(v6, v7, &a2h[3], &a2l[3]);
                int kcol = (half * 8 + ap) * 16;
#pragma unroll
                for (int np = 0; np < 4; np++) {
                    int drow = (2 * np + (g >> 1)) * 8 + rr;
                    int ecol = kcol + (g & 1) * 8;
                    uint32_t b2off = (uint32_t)(drow * 528 + ecol * 2);
                    uint32_t b2h[4];
                    uint32_t b2l[4];
                    ldsm4p(b2h, w2h_base + b2off);
                    ldsm4p(b2l, w2l_base + b2off);
                    mma6(acc2[2 * np], acc2[2 * np + 1], a2h, a2l, b2h, b2l);
                }
            }
        }

        size_t base = (size_t)bhi * KNB * DH;
#pragma unroll
        for (int nt2 = 0; nt2 < 8; nt2++) {
            float c0 = acc2[nt2][0];
            float c1 = acc2[nt2][1];
            float c2 = acc2[nt2][2];
            float c3 = acc2[nt2][3];
            float ma = fmaxf(c0, c2);
            float mb = fmaxf(c1, c3);
#pragma unroll
            for (int mk = 4; mk <= 16; mk <<= 1) {
                ma = fmaxf(ma, __shfl_xor_sync(0xFFFFFFFFu, ma, mk));
                mb = fmaxf(mb, __shfl_xor_sync(0xFFFFFFFFu, mb, mk));
            }
            float e0 = expf(c0 - ma);
            float e2 = expf(c2 - ma);
            float e1 = expf(c1 - mb);
            float e3 = expf(c3 - mb);
            float sa = e0 + e2;
            float sc = e1 + e3;
#pragma unroll
            for (int mk = 4; mk <= 16; mk <<= 1) {
                sa += __shfl_xor_sync(0xFFFFFFFFu, sa, mk);
                sc += __shfl_xor_sync(0xFFFFFFFFu, sc, mk);
            }
            float ia = 1.f / sa;
            float ic = 1.f / sc;
            int d0 = nt2 * 8 + 2 * cq;
            *(float2*)&g_attn[base + (size_t)r * DH + d0] = make_float2(e0 * ia, e1 * ic);
            *(float2*)&g_attn[base + (size_t)(r + 8) * DH + d0] = make_float2(e2 * ia, e3 * ic);
        }
        __syncwarp();
    }
}

// ---------------- norm over i (1024 threads: 16 partial sums of 64 i's) ----------------
__global__ void __launch_bounds__(1024)
norm_kernel() {
    int bhj = blockIdx.x;
    int j = bhj & 15;
    int bh = bhj >> 4;
    int t = threadIdx.x;
    int d = t & 63;
    int iq = t >> 6;       // 0..15
    size_t base = (size_t)bh * NPTS * KNB * DH + j * DH + d;
    float s = 0.f;
#pragma unroll 4
    for (int i = iq * 64; i < iq * 64 + 64; i++) {
        float v = g_attn[base + (size_t)i * KNB * DH];
        s += v * v;
    }
    __shared__ float rshared[16][64];
    rshared[iq][d] = s;
    __syncthreads();
    if (t < 64) {
        float acc = 0.f;
#pragma unroll
        for (int k = 0; k < 16; k++) acc += rshared[k][t];
        g_norm[bhj * DH + t] = sqrtf(acc);
    }
}

// ---------------- aggregate ----------------
__global__ void agg_kernel() {
    int t = threadIdx.x;
    int ii = t >> 6;
    int d = t & 63;
    int bhi = blockIdx.x * 4 + ii;
    int i = bhi & 1023;
    int h = (bhi >> 10) & 7;
    int b = bhi >> 13;

    __shared__ int srow[4][KNB];
    if (t < 64) {
        int i2 = t >> 4;
        int j = t & 15;
        srow[i2][j] = gather_row(b, h, (blockIdx.x * 4 + i2) & 1023, j);
    }
    __syncthreads();

    int bh = b * H + h;
    size_t abase = (size_t)bhi * KNB * DH + d;
    float acc = 0.f;
#pragma unroll
    for (int j = 0; j < KNB; j++) {
        float a = g_attn[abase + j * DH];
        float nm = g_norm[(bh * KNB + j) * DH + d];
        a /= fmaxf(nm, 1e-12f);
        float vg = g_vh[srow[ii][j] + d] +
                   g_rpe[(size_t)((b * NPTS + i) * KNB + j) * INNER + h * DH + d];
        acc = fmaf(a, vg, acc);
    }
    g_agg[(b * NPTS + i) * INNER + h * DH + d] = acc;
}

// ---------------- launch ----------------
extern "C" void kernel_launch(void* const* d_in, const int* in_sizes, int n_in,
                              void* d_out, int out_size) {
    const float* query     = (const float*)d_in[0];
    const float* key_in    = (const float*)d_in[1];
    const float* value     = (const float*)d_in[2];
    const float* canonical = (const float*)d_in[3];
    const float* w_q       = (const float*)d_in[4];
    const float* w_k       = (const float*)d_in[5];
    const float* w_v       = (const float*)d_in[6];
    const float* w_out     = (const float*)d_in[7];
    const float* b_out     = (const float*)d_in[8];
    const float* pos_w1    = (const float*)d_in[9];
    const float* pos_b1    = (const float*)d_in[10];
    const float* pos_w2    = (const float*)d_in[11];
    const float* pos_b2    = (const float*)d_in[12];
    const float* aw1       = (const float*)d_in[13];
    const float* ab1       = (const float*)d_in[14];
    const float* aw2       = (const float*)d_in[15];
    const float* ab2       = (const float*)d_in[16];
    float* out = (float*)d_out;

    float* h1;  cudaGetSymbolAddress((void**)&h1,  g_h1);
    float* rpe; cudaGetSymbolAddress((void**)&rpe, g_rpe);
    float* agg; cudaGetSymbolAddress((void**)&agg, g_agg);

    cudaFuncSetAttribute(attn_tc_kernel,
                         cudaFuncAttributeMaxDynamicSharedMemorySize, AT_SMEM);

    // fused prologue: proj + knn + wprep (independent work, one wave)
    pre_kernel<<<1088, 256>>>(query, w_q, key_in, w_k, value, w_v,
                              canonical, aw1, aw2);

    h1_kernel<<<BS * NPTS, 256>>>(canonical, pos_w1, pos_b1);

    dim3 rgrid(8, 64);
    rpe_gemm<<<rgrid, 256>>>(h1, pos_w2, pos_b2, rpe);

    attn_tc_kernel<<<BS * H * NPTS / 16, 256, AT_SMEM>>>(ab1, ab2);
    norm_kernel<<<BS * H * KNB, 1024>>>();
    agg_kernel<<<BS * H * NPTS / 4, 256>>>();

    dim3 ogrid(8, 32, 1);
    out_gemm<<<ogrid, 256>>>(agg, w_out, b_out, out);
}